// round 9
// baseline (speedup 1.0000x reference)
#include <cuda_runtime.h>
#include <math.h>
#include <stdint.h>

// Problem constants
#define L_   32
#define B_   4
#define N_   1000
#define D_   128
#define K_   8
#define H_   8
#define DH_  16
#define M_   (L_ * B_ * N_)   // 128000 tokens

// Permuted token layout everywhere downstream of the projection:
//   p = (b*N_ + n)*32 + l     (32 temporal positions contiguous)

// Scratch (device globals: allocation-free, graph-capturable)
__device__ float g_spat[(size_t)M_ * 384];   // sq|sk|sv per permuted token (~196MB)
__device__ float g_att [(size_t)M_ * 256];   // [o | so] per permuted token (~131MB)
__device__ float g_w   [768 * 128];          // concat in-weights [768][128]
__device__ float g_wo  [128 * 256];          // concat out-weights [128][256]
__device__ float g_b   [768];                // concat in-biases
__device__ float g_ob  [128];                // t_out_b + s_out_b

// ---------------------------------------------------------------------------
// Pack weights/biases into contiguous buffers
// ---------------------------------------------------------------------------
__global__ void prep_weights(const float* __restrict__ t_in_w,
                             const float* __restrict__ t_in_b,
                             const float* __restrict__ s_in_w,
                             const float* __restrict__ s_in_b,
                             const float* __restrict__ t_out_w,
                             const float* __restrict__ t_out_b,
                             const float* __restrict__ s_out_w,
                             const float* __restrict__ s_out_b)
{
    int i = blockIdx.x * 256 + threadIdx.x;
    const int NW = 384 * 128;                 // 49152
    if (i < NW) {
        g_w[i] = t_in_w[i];
    } else if (i < 2 * NW) {
        g_w[i] = s_in_w[i - NW];
    } else if (i < 2 * NW + 128 * 256) {
        int j = i - 2 * NW;
        int n = j >> 8;
        int k = j & 255;
        g_wo[j] = (k < 128) ? t_out_w[n * 128 + k] : s_out_w[n * 128 + (k - 128)];
    } else {
        int j = i - (2 * NW + 128 * 256);
        if (j < 384)      g_b[j] = t_in_b[j];
        else if (j < 768) g_b[j] = s_in_b[j - 384];
        else if (j < 896) g_ob[j - 768] = t_out_b[j - 768] + s_out_b[j - 768];
    }
}

// ---------------------------------------------------------------------------
// TF32 tensor-core helpers
// ---------------------------------------------------------------------------
__device__ __forceinline__ uint32_t f2tf32(float f)
{
    uint32_t r;
    asm("cvt.rna.tf32.f32 %0, %1;" : "=r"(r) : "f"(f));
    return r;
}

__device__ __forceinline__ void mma_tf32(float* d, const uint32_t* a, const uint32_t* b)
{
    asm volatile(
        "mma.sync.aligned.m16n8k8.row.col.f32.tf32.tf32.f32 "
        "{%0,%1,%2,%3}, {%4,%5,%6,%7}, {%8,%9}, {%0,%1,%2,%3};"
        : "+f"(d[0]), "+f"(d[1]), "+f"(d[2]), "+f"(d[3])
        : "r"(a[0]), "r"(a[1]), "r"(a[2]), "r"(a[3]), "r"(b[0]), "r"(b[1]));
}

// ---------------------------------------------------------------------------
// Fused projection + temporal attention.
// One block per 64 permuted rows = 2 complete (b,n) groups x 32 l.
// GEMM: M-tile 64, N-tile 128, K=128. 8 warps in 2(m) x 4(n), warp tile 32x32.
// nt = 0,1,2 (q,k,v)   -> smem; after nt=2 run 32x32 attention -> g_att[:,0:128]
// nt = 3,4,5 (sq,sk,sv)-> g_spat
// Smem: As 64x132 tf32 | Bs 128x132 tf32 | qkv 3 x 64x132 f32  = ~203KB
// ---------------------------------------------------------------------------
#define FP_SMEM ((64 * 132 + 128 * 132 + 3 * 64 * 132) * 4)

__global__ void __launch_bounds__(256) fused_proj_temporal(const float* __restrict__ x)
{
    extern __shared__ uint32_t sm[];
    uint32_t* As  = sm;                      // [64][132]
    uint32_t* Bs  = sm + 64 * 132;           // [128][132]
    float*    qkv = (float*)(sm + 64 * 132 + 128 * 132);  // [3][64][132]

    const int tid   = threadIdx.x;
    const int warp  = tid >> 5;
    const int lane  = tid & 31;
    const int group = lane >> 2;
    const int tg    = lane & 3;
    const int wm    = (warp & 1) * 32;
    const int wn    = (warp >> 1) * 32;

    const int p0 = blockIdx.x * 64;

    // ---- Load A tile once (row gather from original x layout) ----
    {
        int r  = tid >> 2;            // 0..63 (permuted row within tile)
        int cq = (tid & 3) * 32;      // col base
        int p  = p0 + r;
        int l  = p & 31;
        int bn = p >> 5;
        int b  = bn / N_;
        int n  = bn % N_;
        const float* xr = x + (((size_t)l * B_ + b) * N_ + n) * 128 + cq;
        uint32_t* dst = As + r * 132 + cq;
        #pragma unroll
        for (int i = 0; i < 8; i++) {
            float4 a = *(const float4*)(xr + i * 4);
            *(uint4*)(dst + i * 4) =
                make_uint4(f2tf32(a.x), f2tf32(a.y), f2tf32(a.z), f2tf32(a.w));
        }
    }

    const int trow = tid >> 1;
    const int tcol = (tid & 1) * 64;

    for (int nt = 0; nt < 6; nt++) {
        if (nt) __syncthreads();   // prior mma done reading Bs (and attn done)
        // ---- Load weight tile nt ----
        {
            const float* Bg = g_w + (nt * 128 + trow) * 128 + tcol;
            uint32_t* Bsp = Bs + trow * 132 + tcol;
            #pragma unroll
            for (int i = 0; i < 16; i++) {
                float4 b = *(const float4*)(Bg + i * 4);
                *(uint4*)(Bsp + i * 4) =
                    make_uint4(f2tf32(b.x), f2tf32(b.y), f2tf32(b.z), f2tf32(b.w));
            }
        }
        __syncthreads();

        float acc[2][4][4];
        #pragma unroll
        for (int mi = 0; mi < 2; mi++)
            #pragma unroll
            for (int ni = 0; ni < 4; ni++)
                #pragma unroll
                for (int r = 0; r < 4; r++) acc[mi][ni][r] = 0.f;

        #pragma unroll
        for (int k0 = 0; k0 < 128; k0 += 8) {
            uint32_t af[2][4];
            uint32_t bf[4][2];
            #pragma unroll
            for (int mi = 0; mi < 2; mi++) {
                const uint32_t* p = As + (wm + mi * 16 + group) * 132 + k0 + tg;
                af[mi][0] = p[0];
                af[mi][1] = p[8 * 132];
                af[mi][2] = p[4];
                af[mi][3] = p[8 * 132 + 4];
            }
            #pragma unroll
            for (int ni = 0; ni < 4; ni++) {
                const uint32_t* p = Bs + (wn + ni * 8 + group) * 132 + k0 + tg;
                bf[ni][0] = p[0];
                bf[ni][1] = p[4];
            }
            #pragma unroll
            for (int mi = 0; mi < 2; mi++)
                #pragma unroll
                for (int ni = 0; ni < 4; ni++)
                    mma_tf32(acc[mi][ni], af[mi], bf[ni]);
        }

        // ---- Epilogue ----
        const int row0 = wm + group;
        const int col0 = wn + tg * 2;
        if (nt < 3) {
            float* dst = qkv + nt * (64 * 132);
            #pragma unroll
            for (int ni = 0; ni < 4; ni++) {
                int c = col0 + ni * 8;
                float b0 = g_b[nt * 128 + c], b1 = g_b[nt * 128 + c + 1];
                #pragma unroll
                for (int mi = 0; mi < 2; mi++) {
                    int r = row0 + mi * 16;
                    dst[r * 132 + c]           = acc[mi][ni][0] + b0;
                    dst[r * 132 + c + 1]       = acc[mi][ni][1] + b1;
                    dst[(r + 8) * 132 + c]     = acc[mi][ni][2] + b0;
                    dst[(r + 8) * 132 + c + 1] = acc[mi][ni][3] + b1;
                }
            }
        } else {
            int coff = (nt - 3) * 128;
            #pragma unroll
            for (int ni = 0; ni < 4; ni++) {
                int c = col0 + ni * 8;
                float b0 = g_b[nt * 128 + c], b1 = g_b[nt * 128 + c + 1];
                #pragma unroll
                for (int mi = 0; mi < 2; mi++) {
                    int r = row0 + mi * 16;
                    *(float2*)&g_spat[(size_t)(p0 + r) * 384 + coff + c] =
                        make_float2(acc[mi][ni][0] + b0, acc[mi][ni][1] + b1);
                    *(float2*)&g_spat[(size_t)(p0 + r + 8) * 384 + coff + c] =
                        make_float2(acc[mi][ni][2] + b0, acc[mi][ni][3] + b1);
                }
            }
        }

        // ---- After v is in smem: temporal attention ----
        if (nt == 2) {
            __syncthreads();   // q,k,v all visible
            float* q_s = qkv;
            float* k_s = qkv + 64 * 132;
            float* v_s = qkv + 2 * 64 * 132;

            #pragma unroll
            for (int u = 0; u < 2; u++) {
                int ug   = warp * 2 + u;       // 0..15
                int bnl  = ug >> 3;            // which of the 2 (b,n) groups
                int h    = ug & 7;
                int hoff = h * DH_;
                int base = bnl * 32;

                float4 q[4];
                #pragma unroll
                for (int i = 0; i < 4; i++)
                    q[i] = *(const float4*)(q_s + (base + lane) * 132 + hoff + i * 4);

                float s[32];
                #pragma unroll
                for (int mm = 0; mm < 32; mm++) {
                    const float* kr = k_s + (base + mm) * 132 + hoff;
                    float a = 0.f;
                    #pragma unroll
                    for (int i = 0; i < 4; i++) {
                        float4 kv = *(const float4*)(kr + i * 4);  // broadcast
                        a += q[i].x * kv.x + q[i].y * kv.y + q[i].z * kv.z + q[i].w * kv.w;
                    }
                    s[mm] = a * 0.25f;
                }

                float mx = s[0];
                #pragma unroll
                for (int mm = 1; mm < 32; mm++) mx = fmaxf(mx, s[mm]);
                float sum = 0.f;
                #pragma unroll
                for (int mm = 0; mm < 32; mm++) { s[mm] = __expf(s[mm] - mx); sum += s[mm]; }
                float inv = 1.f / sum;

                float4 o[4];
                #pragma unroll
                for (int i = 0; i < 4; i++) o[i] = make_float4(0.f, 0.f, 0.f, 0.f);
                #pragma unroll
                for (int mm = 0; mm < 32; mm++) {
                    float pb = s[mm] * inv;
                    const float* vr = v_s + (base + mm) * 132 + hoff;
                    #pragma unroll
                    for (int i = 0; i < 4; i++) {
                        float4 vv = *(const float4*)(vr + i * 4);  // broadcast
                        o[i].x += pb * vv.x; o[i].y += pb * vv.y;
                        o[i].z += pb * vv.z; o[i].w += pb * vv.w;
                    }
                }

                float* orow = g_att + (size_t)(p0 + base + lane) * 256 + hoff;
                #pragma unroll
                for (int i = 0; i < 4; i++) *(float4*)(orow + i * 4) = o[i];
            }
            // top-of-loop __syncthreads() at nt=3 orders attn before Bs reuse
        }
    }
}

// ---------------------------------------------------------------------------
// Spatial attention, register-only: one warp per permuted token p (all heads).
// Lane owns dims [4*lane, 4*lane+4) of head h = lane>>2. Scores via 4-lane
// shfl_xor reduction; sv fragments in registers; per-lane softmax (no smem).
// Output -> g_att cols [128,256).
// ---------------------------------------------------------------------------
__global__ void __launch_bounds__(256) spatial_attn(const int* __restrict__ route)
{
    const int tid  = threadIdx.x;
    const int w    = tid >> 5;
    const int lane = tid & 31;
    const size_t p = (size_t)blockIdx.x * 8 + w;
    const int bn   = (int)(p >> 5);
    const int n    = bn % N_;
    const size_t base = p - (size_t)n * 32;    // row of (b, nb=0, l)

    // sq fragment (coalesced 512B)
    float4 q4 = *(const float4*)(g_spat + p * 384 + lane * 4);

    int nbv = (lane < 8) ? route[n * 8 + lane] : 0;

    float s[8];
    float4 v4[8];
    #pragma unroll
    for (int kk = 0; kk < 8; kk++) {
        int nb = __shfl_sync(0xffffffffu, nbv, kk);
        const float* r = g_spat + (base + (size_t)nb * 32) * 384;
        float4 k4 = *(const float4*)(r + 128 + lane * 4);
        v4[kk]    = *(const float4*)(r + 256 + lane * 4);
        float part = q4.x * k4.x + q4.y * k4.y + q4.z * k4.z + q4.w * k4.w;
        part += __shfl_xor_sync(0xffffffffu, part, 1);
        part += __shfl_xor_sync(0xffffffffu, part, 2);   // all 4 lanes of head have it
        s[kk] = part * 0.25f;
    }

    float mx = s[0];
    #pragma unroll
    for (int kk = 1; kk < 8; kk++) mx = fmaxf(mx, s[kk]);
    float sum = 0.f;
    #pragma unroll
    for (int kk = 0; kk < 8; kk++) { s[kk] = __expf(s[kk] - mx); sum += s[kk]; }
    float inv = 1.f / sum;

    float4 o = make_float4(0.f, 0.f, 0.f, 0.f);
    #pragma unroll
    for (int kk = 0; kk < 8; kk++) {
        float pb = s[kk] * inv;
        o.x += pb * v4[kk].x; o.y += pb * v4[kk].y;
        o.z += pb * v4[kk].z; o.w += pb * v4[kk].w;
    }
    *(float4*)(g_att + p * 256 + 128 + lane * 4) = o;
}

// ---------------------------------------------------------------------------
// Output GEMM (KTOT=256) with row scatter: A = g_att (permuted rows),
// C rows written at original token index m = ((l*B+b)*N+n).
// ---------------------------------------------------------------------------
#define GEMM_SMEM (2 * 128 * 132 * 4)

__global__ void __launch_bounds__(256) tf32_gemm_out(float* __restrict__ C)
{
    extern __shared__ uint32_t sm[];
    uint32_t* As = sm;
    uint32_t* Bs = sm + 128 * 132;

    const int tid   = threadIdx.x;
    const int warp  = tid >> 5;
    const int lane  = tid & 31;
    const int group = lane >> 2;
    const int tg    = lane & 3;
    const int wm    = (warp & 1) * 64;
    const int wn    = (warp >> 1) * 32;

    const int trow = tid >> 1;
    const int tcol = (tid & 1) * 64;

    const size_t arow0 = (size_t)blockIdx.x * 128;

    float acc[4][4][4];
    #pragma unroll
    for (int mi = 0; mi < 4; mi++)
        #pragma unroll
        for (int ni = 0; ni < 4; ni++)
            #pragma unroll
            for (int r = 0; r < 4; r++) acc[mi][ni][r] = 0.f;

    #pragma unroll
    for (int kc = 0; kc < 256; kc += 128) {
        if (kc) __syncthreads();

        const float* Ag = g_att + (arow0 + trow) * 256 + kc + tcol;
        const float* Bg = g_wo + (size_t)trow * 256 + kc + tcol;  // g_wo: [128][256]
        uint32_t* Asp = As + trow * 132 + tcol;
        uint32_t* Bsp = Bs + trow * 132 + tcol;
        #pragma unroll
        for (int i = 0; i < 16; i++) {
            float4 a = *(const float4*)(Ag + i * 4);
            float4 b = *(const float4*)(Bg + i * 4);
            *(uint4*)(Asp + i * 4) = make_uint4(f2tf32(a.x), f2tf32(a.y), f2tf32(a.z), f2tf32(a.w));
            *(uint4*)(Bsp + i * 4) = make_uint4(f2tf32(b.x), f2tf32(b.y), f2tf32(b.z), f2tf32(b.w));
        }
        __syncthreads();

        #pragma unroll
        for (int k0 = 0; k0 < 128; k0 += 8) {
            uint32_t af[4][4];
            uint32_t bf[4][2];
            #pragma unroll
            for (int mi = 0; mi < 4; mi++) {
                const uint32_t* p = As + (wm + mi * 16 + group) * 132 + k0 + tg;
                af[mi][0] = p[0];
                af[mi][1] = p[8 * 132];
                af[mi][2] = p[4];
                af[mi][3] = p[8 * 132 + 4];
            }
            #pragma unroll
            for (int ni = 0; ni < 4; ni++) {
                const uint32_t* p = Bs + (wn + ni * 8 + group) * 132 + k0 + tg;
                bf[ni][0] = p[0];
                bf[ni][1] = p[4];
            }
            #pragma unroll
            for (int mi = 0; mi < 4; mi++)
                #pragma unroll
                for (int ni = 0; ni < 4; ni++)
                    mma_tf32(acc[mi][ni], af[mi], bf[ni]);
        }
    }

    const int prow0 = (int)arow0 + wm + group;
    const int col0  = wn + tg * 2;
    #pragma unroll
    for (int mi = 0; mi < 4; mi++) {
        #pragma unroll
        for (int half = 0; half < 2; half++) {
            int pr = prow0 + mi * 16 + half * 8;
            int l  = pr & 31;
            int bn = pr >> 5;
            int b  = bn / N_;
            int n  = bn % N_;
            size_t m = ((size_t)l * B_ + b) * N_ + n;
            #pragma unroll
            for (int ni = 0; ni < 4; ni++) {
                int c = col0 + ni * 8;
                float b0 = g_ob[c], b1 = g_ob[c + 1];
                *(float2*)&C[m * 128 + c] =
                    make_float2(acc[mi][ni][half * 2] + b0, acc[mi][ni][half * 2 + 1] + b1);
            }
        }
    }
}

// ---------------------------------------------------------------------------
extern "C" void kernel_launch(void* const* d_in, const int* in_sizes, int n_in,
                              void* d_out, int out_size)
{
    const float* x       = (const float*)d_in[0];
    const int*   route   = (const int*)  d_in[1];
    const float* t_in_w  = (const float*)d_in[2];
    const float* t_in_b  = (const float*)d_in[3];
    const float* t_out_w = (const float*)d_in[4];
    const float* t_out_b = (const float*)d_in[5];
    const float* s_in_w  = (const float*)d_in[6];
    const float* s_in_b  = (const float*)d_in[7];
    const float* s_out_w = (const float*)d_in[8];
    const float* s_out_b = (const float*)d_in[9];
    float* out = (float*)d_out;

    cudaFuncSetAttribute(fused_proj_temporal, cudaFuncAttributeMaxDynamicSharedMemorySize, FP_SMEM);
    cudaFuncSetAttribute(tf32_gemm_out,       cudaFuncAttributeMaxDynamicSharedMemorySize, GEMM_SMEM);

    // 1) pack weights
    prep_weights<<<516, 256>>>(t_in_w, t_in_b, s_in_w, s_in_b,
                               t_out_w, t_out_b, s_out_w, s_out_b);

    // 2) fused projection + temporal attention (permuted layout)
    fused_proj_temporal<<<M_ / 64, 256, FP_SMEM>>>(x);

    // 3) spatial attention (warp per token, register-only) -> g_att[:,128:256]
    spatial_attn<<<M_ / 8, 256>>>(route);

    // 4) out = g_att(perm) @ g_wo^T + g_ob, rows scattered to original order
    tf32_gemm_out<<<M_ / 128, 256, GEMM_SMEM>>>(out);
}

// round 10
// speedup vs baseline: 1.3390x; 1.3390x over previous
#include <cuda_runtime.h>
#include <math.h>
#include <stdint.h>

// Problem constants
#define L_   32
#define B_   4
#define N_   1000
#define D_   128
#define K_   8
#define H_   8
#define DH_  16
#define M_   (L_ * B_ * N_)   // 128000 tokens
#define PROJW 768             // q|k|v|sq|sk|sv concatenated per token

// Scratch (device globals: allocation-free, graph-capturable)
__device__ float g_proj[(size_t)M_ * PROJW];  // ~393 MB
__device__ float g_att [(size_t)M_ * 256];    // [o | so] fused attn outputs
__device__ float g_w   [PROJW * 128];         // concat in-weights [768][128]
__device__ float g_wo  [128 * 256];           // concat out-weights [128][256]
__device__ float g_b   [PROJW];               // concat in-biases
__device__ float g_ob  [128];                 // t_out_b + s_out_b

// ---------------------------------------------------------------------------
// Pack weights/biases into contiguous buffers
// ---------------------------------------------------------------------------
__global__ void prep_weights(const float* __restrict__ t_in_w,
                             const float* __restrict__ t_in_b,
                             const float* __restrict__ s_in_w,
                             const float* __restrict__ s_in_b,
                             const float* __restrict__ t_out_w,
                             const float* __restrict__ t_out_b,
                             const float* __restrict__ s_out_w,
                             const float* __restrict__ s_out_b)
{
    int i = blockIdx.x * 256 + threadIdx.x;
    const int NW = 384 * 128;                 // 49152
    if (i < NW) {
        g_w[i] = t_in_w[i];
    } else if (i < 2 * NW) {
        g_w[i] = s_in_w[i - NW];
    } else if (i < 2 * NW + 128 * 256) {
        int j = i - 2 * NW;
        int n = j >> 8;
        int k = j & 255;
        g_wo[j] = (k < 128) ? t_out_w[n * 128 + k] : s_out_w[n * 128 + (k - 128)];
    } else {
        int j = i - (2 * NW + 128 * 256);
        if (j < 384)      g_b[j] = t_in_b[j];
        else if (j < 768) g_b[j] = s_in_b[j - 384];
        else if (j < 896) g_ob[j - 768] = t_out_b[j - 768] + s_out_b[j - 768];
    }
}

// ---------------------------------------------------------------------------
// TF32 tensor-core helpers
// ---------------------------------------------------------------------------
__device__ __forceinline__ uint32_t f2tf32(float f)
{
    uint32_t r;
    asm("cvt.rna.tf32.f32 %0, %1;" : "=r"(r) : "f"(f));
    return r;
}

__device__ __forceinline__ void mma_tf32(float* d, const uint32_t* a, const uint32_t* b)
{
    asm volatile(
        "mma.sync.aligned.m16n8k8.row.col.f32.tf32.tf32.f32 "
        "{%0,%1,%2,%3}, {%4,%5,%6,%7}, {%8,%9}, {%0,%1,%2,%3};"
        : "+f"(d[0]), "+f"(d[1]), "+f"(d[2]), "+f"(d[3])
        : "r"(a[0]), "r"(a[1]), "r"(a[2]), "r"(a[3]), "r"(b[0]), "r"(b[1]));
}

// ---------------------------------------------------------------------------
// Projection GEMM, A-resident, B chunked for occupancy.
// One block per 128 rows of x. As holds full K=128 (loaded once, 67.6KB).
// B processed as 6 weight tiles x 2 k-chunks of 64 (Bs 128x68, 34KB).
// Total smem 100KB -> 2 CTAs/SM. 8 warps 2(m)x4(n), warp tile 64x32.
// g_proj[m][c] = sum_k x[m][k] * g_w[c][k] + g_b[c]
// ---------------------------------------------------------------------------
#define PROJ_SMEM ((128 * 132 + 128 * 68) * 4)

__global__ void __launch_bounds__(256, 2) tf32_gemm_proj(const float* __restrict__ A)
{
    extern __shared__ uint32_t sm[];
    uint32_t* As = sm;               // [128][132]
    uint32_t* Bs = sm + 128 * 132;   // [128][68]

    const int tid   = threadIdx.x;
    const int warp  = tid >> 5;
    const int lane  = tid & 31;
    const int group = lane >> 2;
    const int tg    = lane & 3;
    const int wm    = (warp & 1) * 64;
    const int wn    = (warp >> 1) * 32;

    const size_t arow0 = (size_t)blockIdx.x * 128;

    // ---- Load A tile once (full K) ----
    {
        const int trow = tid >> 1;
        const int tcol = (tid & 1) * 64;
        const float* Ag = A + (arow0 + trow) * 128 + tcol;
        uint32_t* Asp = As + trow * 132 + tcol;
        #pragma unroll
        for (int i = 0; i < 16; i++) {
            float4 a = *(const float4*)(Ag + i * 4);
            *(uint4*)(Asp + i * 4) =
                make_uint4(f2tf32(a.x), f2tf32(a.y), f2tf32(a.z), f2tf32(a.w));
        }
    }

    const int brow = tid >> 1;            // 0..127
    const int bcol = (tid & 1) * 32;      // 0 or 32 within 64-chunk

    for (int nt = 0; nt < 6; nt++) {
        float acc[4][4][4];
        #pragma unroll
        for (int mi = 0; mi < 4; mi++)
            #pragma unroll
            for (int ni = 0; ni < 4; ni++)
                #pragma unroll
                for (int r = 0; r < 4; r++) acc[mi][ni][r] = 0.f;

        #pragma unroll
        for (int kc = 0; kc < 128; kc += 64) {
            __syncthreads();   // prior MMA done with Bs (also orders A store, 1st iter)
            // Load B chunk: rows 0..127 of weight tile nt, cols kc..kc+63
            {
                const float* Bg = g_w + (nt * 128 + brow) * 128 + kc + bcol;
                uint32_t* Bsp = Bs + brow * 68 + bcol;
                #pragma unroll
                for (int i = 0; i < 8; i++) {
                    float4 b = *(const float4*)(Bg + i * 4);
                    *(uint4*)(Bsp + i * 4) =
                        make_uint4(f2tf32(b.x), f2tf32(b.y), f2tf32(b.z), f2tf32(b.w));
                }
            }
            __syncthreads();

            #pragma unroll
            for (int k0 = 0; k0 < 64; k0 += 8) {
                uint32_t af[4][4];
                uint32_t bf[4][2];
                #pragma unroll
                for (int mi = 0; mi < 4; mi++) {
                    const uint32_t* p = As + (wm + mi * 16 + group) * 132 + kc + k0 + tg;
                    af[mi][0] = p[0];
                    af[mi][1] = p[8 * 132];
                    af[mi][2] = p[4];
                    af[mi][3] = p[8 * 132 + 4];
                }
                #pragma unroll
                for (int ni = 0; ni < 4; ni++) {
                    const uint32_t* p = Bs + (wn + ni * 8 + group) * 68 + k0 + tg;
                    bf[ni][0] = p[0];
                    bf[ni][1] = p[4];
                }
                #pragma unroll
                for (int mi = 0; mi < 4; mi++)
                    #pragma unroll
                    for (int ni = 0; ni < 4; ni++)
                        mma_tf32(acc[mi][ni], af[mi], bf[ni]);
            }
        }

        // ---- Epilogue for weight tile nt ----
        const int row0 = (int)arow0 + wm + group;
        const int col0 = wn + tg * 2;
        #pragma unroll
        for (int ni = 0; ni < 4; ni++) {
            int c  = col0 + ni * 8;
            int cg = nt * 128 + c;
            float b0 = g_b[cg], b1 = g_b[cg + 1];
            #pragma unroll
            for (int mi = 0; mi < 4; mi++) {
                int r = row0 + mi * 16;
                *(float2*)&g_proj[(size_t)r * PROJW + cg] =
                    make_float2(acc[mi][ni][0] + b0, acc[mi][ni][1] + b1);
                *(float2*)&g_proj[(size_t)(r + 8) * PROJW + cg] =
                    make_float2(acc[mi][ni][2] + b0, acc[mi][ni][3] + b1);
            }
        }
    }
}

// ---------------------------------------------------------------------------
// Output GEMM: out = g_att(128000x256) @ g_wo^T(256->128) + g_ob.
// K=256 processed in 4 chunks of 64; As/Bs 128x68 each (69.6KB -> 2 CTAs/SM).
// ---------------------------------------------------------------------------
#define OUT_SMEM (2 * 128 * 68 * 4)

__global__ void __launch_bounds__(256, 2) tf32_gemm_out(float* __restrict__ C)
{
    extern __shared__ uint32_t sm[];
    uint32_t* As = sm;               // [128][68]
    uint32_t* Bs = sm + 128 * 68;    // [128][68]

    const int tid   = threadIdx.x;
    const int warp  = tid >> 5;
    const int lane  = tid & 31;
    const int group = lane >> 2;
    const int tg    = lane & 3;
    const int wm    = (warp & 1) * 64;
    const int wn    = (warp >> 1) * 32;

    const int trow = tid >> 1;
    const int tcol = (tid & 1) * 32;

    const size_t arow0 = (size_t)blockIdx.x * 128;

    float acc[4][4][4];
    #pragma unroll
    for (int mi = 0; mi < 4; mi++)
        #pragma unroll
        for (int ni = 0; ni < 4; ni++)
            #pragma unroll
            for (int r = 0; r < 4; r++) acc[mi][ni][r] = 0.f;

    #pragma unroll
    for (int kc = 0; kc < 256; kc += 64) {
        if (kc) __syncthreads();
        {
            const float* Ag = g_att + (arow0 + trow) * 256 + kc + tcol;
            const float* Bg = g_wo + (size_t)trow * 256 + kc + tcol;
            uint32_t* Asp = As + trow * 68 + tcol;
            uint32_t* Bsp = Bs + trow * 68 + tcol;
            #pragma unroll
            for (int i = 0; i < 8; i++) {
                float4 a = *(const float4*)(Ag + i * 4);
                float4 b = *(const float4*)(Bg + i * 4);
                *(uint4*)(Asp + i * 4) = make_uint4(f2tf32(a.x), f2tf32(a.y), f2tf32(a.z), f2tf32(a.w));
                *(uint4*)(Bsp + i * 4) = make_uint4(f2tf32(b.x), f2tf32(b.y), f2tf32(b.z), f2tf32(b.w));
            }
        }
        __syncthreads();

        #pragma unroll
        for (int k0 = 0; k0 < 64; k0 += 8) {
            uint32_t af[4][4];
            uint32_t bf[4][2];
            #pragma unroll
            for (int mi = 0; mi < 4; mi++) {
                const uint32_t* p = As + (wm + mi * 16 + group) * 68 + k0 + tg;
                af[mi][0] = p[0];
                af[mi][1] = p[8 * 68];
                af[mi][2] = p[4];
                af[mi][3] = p[8 * 68 + 4];
            }
            #pragma unroll
            for (int ni = 0; ni < 4; ni++) {
                const uint32_t* p = Bs + (wn + ni * 8 + group) * 68 + k0 + tg;
                bf[ni][0] = p[0];
                bf[ni][1] = p[4];
            }
            #pragma unroll
            for (int mi = 0; mi < 4; mi++)
                #pragma unroll
                for (int ni = 0; ni < 4; ni++)
                    mma_tf32(acc[mi][ni], af[mi], bf[ni]);
        }
    }

    const int row0 = (int)arow0 + wm + group;
    const int col0 = wn + tg * 2;
    #pragma unroll
    for (int ni = 0; ni < 4; ni++) {
        int c = col0 + ni * 8;
        float b0 = g_ob[c], b1 = g_ob[c + 1];
        #pragma unroll
        for (int mi = 0; mi < 4; mi++) {
            int r = row0 + mi * 16;
            *(float2*)&C[(size_t)r * 128 + c] =
                make_float2(acc[mi][ni][0] + b0, acc[mi][ni][1] + b1);
            *(float2*)&C[(size_t)(r + 8) * 128 + c] =
                make_float2(acc[mi][ni][2] + b0, acc[mi][ni][3] + b1);
        }
    }
}

// ---------------------------------------------------------------------------
// Temporal attention: one block per (b, n). Cooperative coalesced load of all
// 32 rows x (q|k|v) into smem, then warp h computes head h (smem reads are
// all-lane broadcasts -> conflict-free). Output -> g_att cols [0,128).
// ---------------------------------------------------------------------------
#define TEMP_STRIDE 388   // 384 + 4 pad (floats)
#define TEMP_SMEM   (32 * TEMP_STRIDE * 4)

__global__ void __launch_bounds__(256) temporal_attn()
{
    extern __shared__ float S[];   // [32][TEMP_STRIDE]

    const int tid  = threadIdx.x;
    const int wid  = tid >> 5;     // head
    const int lane = tid & 31;     // l (temporal position)
    const int n = blockIdx.x % N_;
    const int b = blockIdx.x / N_;

    // Coalesced load: 32 rows x 384 floats (96 float4 per row)
    #pragma unroll
    for (int i = 0; i < 12; i++) {
        int fid = i * 256 + tid;        // 0..3071
        int r   = fid / 96;
        int c4  = fid % 96;
        size_t m = ((size_t)r * B_ + b) * N_ + n;
        float4 v = *(const float4*)(g_proj + m * PROJW + c4 * 4);
        *(float4*)(S + r * TEMP_STRIDE + c4 * 4) = v;
    }
    __syncthreads();

    const int hoff = wid * DH_;
    float4 q[4];
    #pragma unroll
    for (int i = 0; i < 4; i++)
        q[i] = *(const float4*)(S + lane * TEMP_STRIDE + hoff + i * 4);

    float s[32];
    #pragma unroll
    for (int mm = 0; mm < 32; mm++) {
        const float* kr = S + mm * TEMP_STRIDE + 128 + hoff;
        float a = 0.f;
        #pragma unroll
        for (int i = 0; i < 4; i++) {
            float4 kv = *(const float4*)(kr + i * 4);   // broadcast
            a += q[i].x * kv.x + q[i].y * kv.y + q[i].z * kv.z + q[i].w * kv.w;
        }
        s[mm] = a * 0.25f;
    }

    float mx = s[0];
    #pragma unroll
    for (int mm = 1; mm < 32; mm++) mx = fmaxf(mx, s[mm]);
    float sum = 0.f;
    #pragma unroll
    for (int mm = 0; mm < 32; mm++) { s[mm] = __expf(s[mm] - mx); sum += s[mm]; }
    float inv = 1.f / sum;

    float4 o[4];
    #pragma unroll
    for (int i = 0; i < 4; i++) o[i] = make_float4(0.f, 0.f, 0.f, 0.f);
    #pragma unroll
    for (int mm = 0; mm < 32; mm++) {
        float p = s[mm] * inv;
        const float* vr = S + mm * TEMP_STRIDE + 256 + hoff;
        #pragma unroll
        for (int i = 0; i < 4; i++) {
            float4 vv = *(const float4*)(vr + i * 4);   // broadcast
            o[i].x += p * vv.x; o[i].y += p * vv.y;
            o[i].z += p * vv.z; o[i].w += p * vv.w;
        }
    }

    size_t m = ((size_t)lane * B_ + b) * N_ + n;
    float* orow = g_att + m * 256 + hoff;
    #pragma unroll
    for (int i = 0; i < 4; i++) *(float4*)(orow + i * 4) = o[i];
}

// ---------------------------------------------------------------------------
// Spatial attention, register-only: one warp per token m (all 8 heads).
// Lane owns dims [4*lane, 4*lane+4) of head h = lane>>2. Scores via 4-lane
// shfl_xor reduction; sv fragments in registers; per-lane softmax (no smem).
// Output -> g_att cols [128,256).
// ---------------------------------------------------------------------------
__global__ void __launch_bounds__(256) spatial_attn(const int* __restrict__ route)
{
    const int tid  = threadIdx.x;
    const int w    = tid >> 5;
    const int lane = tid & 31;
    const size_t m = (size_t)blockIdx.x * 8 + w;
    const int n    = (int)(m % N_);
    const size_t lbbase = m - n;               // row of (l, b, 0)

    // sq fragment (coalesced 512B per warp)
    float4 q4 = *(const float4*)(g_proj + m * PROJW + 384 + lane * 4);

    int nbv = (lane < 8) ? route[n * 8 + lane] : 0;

    float s[8];
    float4 v4[8];
    #pragma unroll
    for (int kk = 0; kk < 8; kk++) {
        int nb = __shfl_sync(0xffffffffu, nbv, kk);
        const float* r = g_proj + (lbbase + nb) * PROJW;
        float4 k4 = *(const float4*)(r + 512 + lane * 4);
        v4[kk]    = *(const float4*)(r + 640 + lane * 4);
        float part = q4.x * k4.x + q4.y * k4.y + q4.z * k4.z + q4.w * k4.w;
        part += __shfl_xor_sync(0xffffffffu, part, 1);
        part += __shfl_xor_sync(0xffffffffu, part, 2);   // all 4 lanes of head have it
        s[kk] = part * 0.25f;
    }

    float mx = s[0];
    #pragma unroll
    for (int kk = 1; kk < 8; kk++) mx = fmaxf(mx, s[kk]);
    float sum = 0.f;
    #pragma unroll
    for (int kk = 0; kk < 8; kk++) { s[kk] = __expf(s[kk] - mx); sum += s[kk]; }
    float inv = 1.f / sum;

    float4 o = make_float4(0.f, 0.f, 0.f, 0.f);
    #pragma unroll
    for (int kk = 0; kk < 8; kk++) {
        float pb = s[kk] * inv;
        o.x += pb * v4[kk].x; o.y += pb * v4[kk].y;
        o.z += pb * v4[kk].z; o.w += pb * v4[kk].w;
    }
    *(float4*)(g_att + m * 256 + 128 + lane * 4) = o;
}

// ---------------------------------------------------------------------------
extern "C" void kernel_launch(void* const* d_in, const int* in_sizes, int n_in,
                              void* d_out, int out_size)
{
    const float* x       = (const float*)d_in[0];
    const int*   route   = (const int*)  d_in[1];
    const float* t_in_w  = (const float*)d_in[2];
    const float* t_in_b  = (const float*)d_in[3];
    const float* t_out_w = (const float*)d_in[4];
    const float* t_out_b = (const float*)d_in[5];
    const float* s_in_w  = (const float*)d_in[6];
    const float* s_in_b  = (const float*)d_in[7];
    const float* s_out_w = (const float*)d_in[8];
    const float* s_out_b = (const float*)d_in[9];
    float* out = (float*)d_out;

    cudaFuncSetAttribute(tf32_gemm_proj, cudaFuncAttributeMaxDynamicSharedMemorySize, PROJ_SMEM);
    cudaFuncSetAttribute(tf32_gemm_out,  cudaFuncAttributeMaxDynamicSharedMemorySize, OUT_SMEM);
    cudaFuncSetAttribute(temporal_attn,  cudaFuncAttributeMaxDynamicSharedMemorySize, TEMP_SMEM);

    // 1) pack weights
    prep_weights<<<516, 256>>>(t_in_w, t_in_b, s_in_w, s_in_b,
                               t_out_w, t_out_b, s_out_w, s_out_b);

    // 2) fused projection: x(128000x128) @ g_w^T + g_b -> g_proj
    tf32_gemm_proj<<<M_ / 128, 256, PROJ_SMEM>>>(x);

    // 3) temporal attention (block per (b,n)) -> g_att[:, 0:128]
    temporal_attn<<<B_ * N_, 256, TEMP_SMEM>>>();

    // 4) spatial attention (warp per token, register-only) -> g_att[:, 128:256]
    spatial_attn<<<M_ / 8, 256>>>(route);

    // 5) out = g_att @ g_wo^T + g_ob
    tf32_gemm_out<<<M_ / 128, 256, OUT_SMEM>>>(out);
}

// round 11
// speedup vs baseline: 1.7769x; 1.3271x over previous
#include <cuda_runtime.h>
#include <math.h>
#include <stdint.h>

// Problem constants
#define L_   32
#define B_   4
#define N_   1000
#define D_   128
#define K_   8
#define H_   8
#define DH_  16
#define M_   (L_ * B_ * N_)   // 128000 tokens
#define PROJW 768             // q|k|v|sq|sk|sv concatenated per token

// Scratch (device globals: allocation-free, graph-capturable)
__device__ float g_proj[(size_t)M_ * PROJW];  // ~393 MB (fp32)
__device__ float g_att [(size_t)M_ * 256];    // [o | so], stored tf32-rounded
__device__ float g_w   [PROJW * 128];         // concat in-weights, tf32-rounded
__device__ float g_wo  [128 * 256];           // concat out-weights, tf32-rounded
__device__ float g_b   [PROJW];               // concat in-biases (fp32)
__device__ float g_ob  [128];                 // t_out_b + s_out_b (fp32)

// ---------------------------------------------------------------------------
// TF32 helpers
// ---------------------------------------------------------------------------
__device__ __forceinline__ uint32_t f2tf32(float f)
{
    uint32_t r;
    asm("cvt.rna.tf32.f32 %0, %1;" : "=r"(r) : "f"(f));
    return r;
}
__device__ __forceinline__ float f2tf32f(float f) { return __uint_as_float(f2tf32(f)); }

__device__ __forceinline__ void mma_tf32(float* d, const uint32_t* a, const uint32_t* b)
{
    asm volatile(
        "mma.sync.aligned.m16n8k8.row.col.f32.tf32.tf32.f32 "
        "{%0,%1,%2,%3}, {%4,%5,%6,%7}, {%8,%9}, {%0,%1,%2,%3};"
        : "+f"(d[0]), "+f"(d[1]), "+f"(d[2]), "+f"(d[3])
        : "r"(a[0]), "r"(a[1]), "r"(a[2]), "r"(a[3]), "r"(b[0]), "r"(b[1]));
}

__device__ __forceinline__ void cp16(uint32_t dst_smem, const void* src)
{
    asm volatile("cp.async.ca.shared.global [%0], [%1], 16;" :: "r"(dst_smem), "l"(src));
}
#define CP_COMMIT()  asm volatile("cp.async.commit_group;")
#define CP_WAIT(n)   asm volatile("cp.async.wait_group %0;" :: "n"(n))

// Swizzled [128][32] tf32 chunk buffer: element (row, col) lives at
//   row*32 + ((col>>2) ^ (row&7))*4 + (col&3)     (16B-aligned copies; LDS conflict-free)

// ---------------------------------------------------------------------------
// Pack weights/biases (weights pre-converted to tf32 bit patterns)
// ---------------------------------------------------------------------------
__global__ void prep_weights(const float* __restrict__ t_in_w,
                             const float* __restrict__ t_in_b,
                             const float* __restrict__ s_in_w,
                             const float* __restrict__ s_in_b,
                             const float* __restrict__ t_out_w,
                             const float* __restrict__ t_out_b,
                             const float* __restrict__ s_out_w,
                             const float* __restrict__ s_out_b)
{
    int i = blockIdx.x * 256 + threadIdx.x;
    const int NW = 384 * 128;                 // 49152
    if (i < NW) {
        g_w[i] = f2tf32f(t_in_w[i]);
    } else if (i < 2 * NW) {
        g_w[i] = f2tf32f(s_in_w[i - NW]);
    } else if (i < 2 * NW + 128 * 256) {
        int j = i - 2 * NW;
        int n = j >> 8;
        int k = j & 255;
        g_wo[j] = f2tf32f((k < 128) ? t_out_w[n * 128 + k] : s_out_w[n * 128 + (k - 128)]);
    } else {
        int j = i - (2 * NW + 128 * 256);
        if (j < 384)      g_b[j] = t_in_b[j];
        else if (j < 768) g_b[j] = s_in_b[j - 384];
        else if (j < 896) g_ob[j - 768] = t_out_b[j - 768] + s_out_b[j - 768];
    }
}

// ---------------------------------------------------------------------------
// Projection GEMM: A resident (128x132, cvt at load), B via cp.async
// double-buffered swizzled 32-k chunks (24 chunks = 6 weight tiles x 4).
// Smem 100.4KB -> 2 CTAs/SM. 8 warps 2(m)x4(n), warp tile 64x32.
// ---------------------------------------------------------------------------
#define PROJ_SMEM ((128 * 132 + 2 * 128 * 32) * 4)

__global__ void __launch_bounds__(256, 2) tf32_gemm_proj(const float* __restrict__ A)
{
    extern __shared__ uint32_t sm[];
    uint32_t* As = sm;                    // [128][132], full K
    uint32_t* Bb = sm + 128 * 132;        // 2 x [128][32] swizzled
    const uint32_t bbase = (uint32_t)__cvta_generic_to_shared(Bb);

    const int tid   = threadIdx.x;
    const int warp  = tid >> 5;
    const int lane  = tid & 31;
    const int group = lane >> 2;
    const int tg    = lane & 3;
    const int wm    = (warp & 1) * 64;
    const int wn    = (warp >> 1) * 32;

    const size_t arow0 = (size_t)blockIdx.x * 128;

    // ---- Load A tile once (full K, cvt to tf32) ----
    {
        const int trow = tid >> 1;
        const int tcol = (tid & 1) * 64;
        const float* Ag = A + (arow0 + trow) * 128 + tcol;
        uint32_t* Asp = As + trow * 132 + tcol;
        #pragma unroll
        for (int i = 0; i < 16; i++) {
            float4 a = *(const float4*)(Ag + i * 4);
            *(uint4*)(Asp + i * 4) =
                make_uint4(f2tf32(a.x), f2tf32(a.y), f2tf32(a.z), f2tf32(a.w));
        }
    }

    // ---- B chunk prefetch (cp.async, swizzled) ----
    auto prefB = [&](int c) {
        int nt = c >> 2, kc = (c & 3) * 32;
        uint32_t base = bbase + (c & 1) * (128 * 32 * 4);
        #pragma unroll
        for (int i = 0; i < 4; i++) {
            int u   = i * 256 + tid;    // 0..1023
            int row = u >> 3;
            int c4  = u & 7;
            const float* src = g_w + (size_t)(nt * 128 + row) * 128 + kc + c4 * 4;
            uint32_t dst = base + (row * 32 + ((c4 ^ (row & 7)) << 2)) * 4;
            cp16(dst, src);
        }
        CP_COMMIT();
    };

    prefB(0);

    float acc[4][4][4];

    for (int c = 0; c < 24; c++) {
        const int nt = c >> 2;
        const int kc = (c & 3) * 32;

        if (c + 1 < 24) { prefB(c + 1); CP_WAIT(1); }
        else            { CP_WAIT(0); }
        __syncthreads();

        if ((c & 3) == 0) {
            #pragma unroll
            for (int mi = 0; mi < 4; mi++)
                #pragma unroll
                for (int ni = 0; ni < 4; ni++)
                    #pragma unroll
                    for (int r = 0; r < 4; r++) acc[mi][ni][r] = 0.f;
        }

        const uint32_t* Bs = Bb + (c & 1) * (128 * 32);

        #pragma unroll
        for (int k0 = 0; k0 < 32; k0 += 8) {
            uint32_t af[4][4];
            uint32_t bf[4][2];
            #pragma unroll
            for (int mi = 0; mi < 4; mi++) {
                const uint32_t* p = As + (wm + mi * 16 + group) * 132 + kc + k0 + tg;
                af[mi][0] = p[0];
                af[mi][1] = p[8 * 132];
                af[mi][2] = p[4];
                af[mi][3] = p[8 * 132 + 4];
            }
            #pragma unroll
            for (int ni = 0; ni < 4; ni++) {
                int row = wn + ni * 8 + group;
                int b0 = ((k0 >> 2) ^ (row & 7)) << 2;
                int b1 = (((k0 >> 2) + 1) ^ (row & 7)) << 2;
                bf[ni][0] = Bs[row * 32 + b0 + tg];
                bf[ni][1] = Bs[row * 32 + b1 + tg];
            }
            #pragma unroll
            for (int mi = 0; mi < 4; mi++)
                #pragma unroll
                for (int ni = 0; ni < 4; ni++)
                    mma_tf32(acc[mi][ni], af[mi], bf[ni]);
        }
        __syncthreads();

        if ((c & 3) == 3) {
            const int row0 = (int)arow0 + wm + group;
            const int col0 = wn + tg * 2;
            #pragma unroll
            for (int ni = 0; ni < 4; ni++) {
                int cc = col0 + ni * 8;
                int cg = nt * 128 + cc;
                float b0 = g_b[cg], b1 = g_b[cg + 1];
                #pragma unroll
                for (int mi = 0; mi < 4; mi++) {
                    int r = row0 + mi * 16;
                    *(float2*)&g_proj[(size_t)r * PROJW + cg] =
                        make_float2(acc[mi][ni][0] + b0, acc[mi][ni][1] + b1);
                    *(float2*)&g_proj[(size_t)(r + 8) * PROJW + cg] =
                        make_float2(acc[mi][ni][2] + b0, acc[mi][ni][3] + b1);
                }
            }
        }
    }
}

// ---------------------------------------------------------------------------
// Output GEMM: out = g_att(128000x256) @ g_wo^T + g_ob.
// Both operands already tf32 bit-patterns -> pure cp.async double-buffered
// swizzled 32-k chunks (8 chunks). Smem 65.5KB -> 2 CTAs/SM.
// ---------------------------------------------------------------------------
#define OUT_SMEM (4 * 128 * 32 * 4)

__global__ void __launch_bounds__(256, 2) tf32_gemm_out(float* __restrict__ C)
{
    extern __shared__ uint32_t sm[];
    uint32_t* Ab = sm;                    // 2 x [128][32]
    uint32_t* Bb = sm + 2 * 128 * 32;     // 2 x [128][32]
    const uint32_t abase = (uint32_t)__cvta_generic_to_shared(Ab);
    const uint32_t bbase = (uint32_t)__cvta_generic_to_shared(Bb);

    const int tid   = threadIdx.x;
    const int warp  = tid >> 5;
    const int lane  = tid & 31;
    const int group = lane >> 2;
    const int tg    = lane & 3;
    const int wm    = (warp & 1) * 64;
    const int wn    = (warp >> 1) * 32;

    const size_t arow0 = (size_t)blockIdx.x * 128;

    auto pref = [&](int c) {
        int kc = c * 32;
        uint32_t ab = abase + (c & 1) * (128 * 32 * 4);
        uint32_t bb = bbase + (c & 1) * (128 * 32 * 4);
        #pragma unroll
        for (int i = 0; i < 4; i++) {
            int u   = i * 256 + tid;
            int row = u >> 3;
            int c4  = u & 7;
            uint32_t off = (row * 32 + ((c4 ^ (row & 7)) << 2)) * 4;
            cp16(ab + off, g_att + (arow0 + row) * 256 + kc + c4 * 4);
            cp16(bb + off, g_wo + (size_t)row * 256 + kc + c4 * 4);
        }
        CP_COMMIT();
    };

    pref(0);

    float acc[4][4][4];
    #pragma unroll
    for (int mi = 0; mi < 4; mi++)
        #pragma unroll
        for (int ni = 0; ni < 4; ni++)
            #pragma unroll
            for (int r = 0; r < 4; r++) acc[mi][ni][r] = 0.f;

    for (int c = 0; c < 8; c++) {
        if (c + 1 < 8) { pref(c + 1); CP_WAIT(1); }
        else           { CP_WAIT(0); }
        __syncthreads();

        const uint32_t* As = Ab + (c & 1) * (128 * 32);
        const uint32_t* Bs = Bb + (c & 1) * (128 * 32);

        #pragma unroll
        for (int k0 = 0; k0 < 32; k0 += 8) {
            uint32_t af[4][4];
            uint32_t bf[4][2];
            #pragma unroll
            for (int mi = 0; mi < 4; mi++) {
                int row = wm + mi * 16 + group;
                int b0 = ((k0 >> 2) ^ (row & 7)) << 2;
                int b1 = (((k0 >> 2) + 1) ^ (row & 7)) << 2;
                int rb0 = ((k0 >> 2) ^ ((row + 8) & 7)) << 2;
                int rb1 = (((k0 >> 2) + 1) ^ ((row + 8) & 7)) << 2;
                af[mi][0] = As[row * 32 + b0 + tg];
                af[mi][1] = As[(row + 8) * 32 + rb0 + tg];
                af[mi][2] = As[row * 32 + b1 + tg];
                af[mi][3] = As[(row + 8) * 32 + rb1 + tg];
            }
            #pragma unroll
            for (int ni = 0; ni < 4; ni++) {
                int row = wn + ni * 8 + group;
                int b0 = ((k0 >> 2) ^ (row & 7)) << 2;
                int b1 = (((k0 >> 2) + 1) ^ (row & 7)) << 2;
                bf[ni][0] = Bs[row * 32 + b0 + tg];
                bf[ni][1] = Bs[row * 32 + b1 + tg];
            }
            #pragma unroll
            for (int mi = 0; mi < 4; mi++)
                #pragma unroll
                for (int ni = 0; ni < 4; ni++)
                    mma_tf32(acc[mi][ni], af[mi], bf[ni]);
        }
        __syncthreads();
    }

    const int row0 = (int)arow0 + wm + group;
    const int col0 = wn + tg * 2;
    #pragma unroll
    for (int ni = 0; ni < 4; ni++) {
        int c = col0 + ni * 8;
        float b0 = g_ob[c], b1 = g_ob[c + 1];
        #pragma unroll
        for (int mi = 0; mi < 4; mi++) {
            int r = row0 + mi * 16;
            *(float2*)&C[(size_t)r * 128 + c] =
                make_float2(acc[mi][ni][0] + b0, acc[mi][ni][1] + b1);
            *(float2*)&C[(size_t)(r + 8) * 128 + c] =
                make_float2(acc[mi][ni][2] + b0, acc[mi][ni][3] + b1);
        }
    }
}

// ---------------------------------------------------------------------------
// Temporal attention: one block per (b, n). Cooperative coalesced load of all
// 32 rows x (q|k|v) into smem, warp h computes head h. Output (tf32-rounded)
// -> g_att cols [0,128).
// ---------------------------------------------------------------------------
#define TEMP_STRIDE 388   // 384 + 4 pad (floats)
#define TEMP_SMEM   (32 * TEMP_STRIDE * 4)

__global__ void __launch_bounds__(256) temporal_attn()
{
    extern __shared__ float S[];   // [32][TEMP_STRIDE]

    const int tid  = threadIdx.x;
    const int wid  = tid >> 5;     // head
    const int lane = tid & 31;     // l (temporal position)
    const int n = blockIdx.x % N_;
    const int b = blockIdx.x / N_;

    #pragma unroll
    for (int i = 0; i < 12; i++) {
        int fid = i * 256 + tid;
        int r   = fid / 96;
        int c4  = fid % 96;
        size_t m = ((size_t)r * B_ + b) * N_ + n;
        float4 v = *(const float4*)(g_proj + m * PROJW + c4 * 4);
        *(float4*)(S + r * TEMP_STRIDE + c4 * 4) = v;
    }
    __syncthreads();

    const int hoff = wid * DH_;
    float4 q[4];
    #pragma unroll
    for (int i = 0; i < 4; i++)
        q[i] = *(const float4*)(S + lane * TEMP_STRIDE + hoff + i * 4);

    float s[32];
    #pragma unroll
    for (int mm = 0; mm < 32; mm++) {
        const float* kr = S + mm * TEMP_STRIDE + 128 + hoff;
        float a = 0.f;
        #pragma unroll
        for (int i = 0; i < 4; i++) {
            float4 kv = *(const float4*)(kr + i * 4);   // broadcast
            a += q[i].x * kv.x + q[i].y * kv.y + q[i].z * kv.z + q[i].w * kv.w;
        }
        s[mm] = a * 0.25f;
    }

    float mx = s[0];
    #pragma unroll
    for (int mm = 1; mm < 32; mm++) mx = fmaxf(mx, s[mm]);
    float sum = 0.f;
    #pragma unroll
    for (int mm = 0; mm < 32; mm++) { s[mm] = __expf(s[mm] - mx); sum += s[mm]; }
    float inv = 1.f / sum;

    float4 o[4];
    #pragma unroll
    for (int i = 0; i < 4; i++) o[i] = make_float4(0.f, 0.f, 0.f, 0.f);
    #pragma unroll
    for (int mm = 0; mm < 32; mm++) {
        float p = s[mm] * inv;
        const float* vr = S + mm * TEMP_STRIDE + 256 + hoff;
        #pragma unroll
        for (int i = 0; i < 4; i++) {
            float4 vv = *(const float4*)(vr + i * 4);   // broadcast
            o[i].x += p * vv.x; o[i].y += p * vv.y;
            o[i].z += p * vv.z; o[i].w += p * vv.w;
        }
    }

    size_t m = ((size_t)lane * B_ + b) * N_ + n;
    float* orow = g_att + m * 256 + hoff;
    #pragma unroll
    for (int i = 0; i < 4; i++)
        *(float4*)(orow + i * 4) =
            make_float4(f2tf32f(o[i].x), f2tf32f(o[i].y), f2tf32f(o[i].z), f2tf32f(o[i].w));
}

// ---------------------------------------------------------------------------
// Spatial attention, register-only: one warp per token m (all 8 heads).
// Output (tf32-rounded) -> g_att cols [128,256).
// ---------------------------------------------------------------------------
__global__ void __launch_bounds__(256) spatial_attn(const int* __restrict__ route)
{
    const int tid  = threadIdx.x;
    const int w    = tid >> 5;
    const int lane = tid & 31;
    const size_t m = (size_t)blockIdx.x * 8 + w;
    const int n    = (int)(m % N_);
    const size_t lbbase = m - n;               // row of (l, b, 0)

    float4 q4 = *(const float4*)(g_proj + m * PROJW + 384 + lane * 4);

    int nbv = (lane < 8) ? route[n * 8 + lane] : 0;

    float s[8];
    float4 v4[8];
    #pragma unroll
    for (int kk = 0; kk < 8; kk++) {
        int nb = __shfl_sync(0xffffffffu, nbv, kk);
        const float* r = g_proj + (lbbase + nb) * PROJW;
        float4 k4 = *(const float4*)(r + 512 + lane * 4);
        v4[kk]    = *(const float4*)(r + 640 + lane * 4);
        float part = q4.x * k4.x + q4.y * k4.y + q4.z * k4.z + q4.w * k4.w;
        part += __shfl_xor_sync(0xffffffffu, part, 1);
        part += __shfl_xor_sync(0xffffffffu, part, 2);
        s[kk] = part * 0.25f;
    }

    float mx = s[0];
    #pragma unroll
    for (int kk = 1; kk < 8; kk++) mx = fmaxf(mx, s[kk]);
    float sum = 0.f;
    #pragma unroll
    for (int kk = 0; kk < 8; kk++) { s[kk] = __expf(s[kk] - mx); sum += s[kk]; }
    float inv = 1.f / sum;

    float4 o = make_float4(0.f, 0.f, 0.f, 0.f);
    #pragma unroll
    for (int kk = 0; kk < 8; kk++) {
        float pb = s[kk] * inv;
        o.x += pb * v4[kk].x; o.y += pb * v4[kk].y;
        o.z += pb * v4[kk].z; o.w += pb * v4[kk].w;
    }
    *(float4*)(g_att + m * 256 + 128 + lane * 4) =
        make_float4(f2tf32f(o.x), f2tf32f(o.y), f2tf32f(o.z), f2tf32f(o.w));
}

// ---------------------------------------------------------------------------
extern "C" void kernel_launch(void* const* d_in, const int* in_sizes, int n_in,
                              void* d_out, int out_size)
{
    const float* x       = (const float*)d_in[0];
    const int*   route   = (const int*)  d_in[1];
    const float* t_in_w  = (const float*)d_in[2];
    const float* t_in_b  = (const float*)d_in[3];
    const float* t_out_w = (const float*)d_in[4];
    const float* t_out_b = (const float*)d_in[5];
    const float* s_in_w  = (const float*)d_in[6];
    const float* s_in_b  = (const float*)d_in[7];
    const float* s_out_w = (const float*)d_in[8];
    const float* s_out_b = (const float*)d_in[9];
    float* out = (float*)d_out;

    cudaFuncSetAttribute(tf32_gemm_proj, cudaFuncAttributeMaxDynamicSharedMemorySize, PROJ_SMEM);
    cudaFuncSetAttribute(tf32_gemm_out,  cudaFuncAttributeMaxDynamicSharedMemorySize, OUT_SMEM);
    cudaFuncSetAttribute(temporal_attn,  cudaFuncAttributeMaxDynamicSharedMemorySize, TEMP_SMEM);

    // 1) pack weights (tf32-rounded)
    prep_weights<<<516, 256>>>(t_in_w, t_in_b, s_in_w, s_in_b,
                               t_out_w, t_out_b, s_out_w, s_out_b);

    // 2) fused projection: x(128000x128) @ g_w^T + g_b -> g_proj
    tf32_gemm_proj<<<M_ / 128, 256, PROJ_SMEM>>>(x);

    // 3) temporal attention (block per (b,n)) -> g_att[:, 0:128]
    temporal_attn<<<B_ * N_, 256, TEMP_SMEM>>>();

    // 4) spatial attention (warp per token, register-only) -> g_att[:, 128:256]
    spatial_attn<<<M_ / 8, 256>>>(route);

    // 5) out = g_att @ g_wo^T + g_ob
    tf32_gemm_out<<<M_ / 128, 256, OUT_SMEM>>>(out);
}

// round 13
// speedup vs baseline: 2.1600x; 1.2156x over previous
#include <cuda_runtime.h>
#include <cuda_fp16.h>
#include <math.h>
#include <stdint.h>

// Problem constants
#define L_   32
#define B_   4
#define N_   1000
#define D_   128
#define K_   8
#define H_   8
#define DH_  16
#define M_   (L_ * B_ * N_)   // 128000 tokens
#define PROJW 768             // q|k|v|sq|sk|sv concatenated per token

// Scratch (device globals: allocation-free, graph-capturable)
__device__ float  g_proj[(size_t)M_ * PROJW];  // ~393 MB (fp32, attention precision)
__device__ __half g_att [(size_t)M_ * 256];    // [o | so] fp16 (GEMM input)
__device__ __half g_w   [PROJW * 128];         // concat in-weights fp16
__device__ __half g_wo  [128 * 256];           // concat out-weights fp16
__device__ float  g_b   [PROJW];               // concat in-biases (fp32)
__device__ float  g_ob  [128];                 // t_out_b + s_out_b (fp32)

// ---------------------------------------------------------------------------
// Helpers
// ---------------------------------------------------------------------------
__device__ __forceinline__ void mma_f16(float* d, const uint32_t* a, const uint32_t* b)
{
    asm volatile(
        "mma.sync.aligned.m16n8k16.row.col.f32.f16.f16.f32 "
        "{%0,%1,%2,%3}, {%4,%5,%6,%7}, {%8,%9}, {%0,%1,%2,%3};"
        : "+f"(d[0]), "+f"(d[1]), "+f"(d[2]), "+f"(d[3])
        : "r"(a[0]), "r"(a[1]), "r"(a[2]), "r"(a[3]), "r"(b[0]), "r"(b[1]));
}

__device__ __forceinline__ void cp16(uint32_t dst_smem, const void* src)
{
    asm volatile("cp.async.ca.shared.global [%0], [%1], 16;" :: "r"(dst_smem), "l"(src));
}
#define CP_COMMIT()  asm volatile("cp.async.commit_group;")
#define CP_WAIT(n)   asm volatile("cp.async.wait_group %0;" :: "n"(n))

// ---------------------------------------------------------------------------
// Pack weights/biases (weights converted to fp16 — same 10-bit mantissa as tf32)
// ---------------------------------------------------------------------------
__global__ void prep_weights(const float* __restrict__ t_in_w,
                             const float* __restrict__ t_in_b,
                             const float* __restrict__ s_in_w,
                             const float* __restrict__ s_in_b,
                             const float* __restrict__ t_out_w,
                             const float* __restrict__ t_out_b,
                             const float* __restrict__ s_out_w,
                             const float* __restrict__ s_out_b)
{
    int i = blockIdx.x * 256 + threadIdx.x;
    const int NW = 384 * 128;                 // 49152
    if (i < NW) {
        g_w[i] = __float2half_rn(t_in_w[i]);
    } else if (i < 2 * NW) {
        g_w[i] = __float2half_rn(s_in_w[i - NW]);
    } else if (i < 2 * NW + 128 * 256) {
        int j = i - 2 * NW;
        int n = j >> 8;
        int k = j & 255;
        g_wo[j] = __float2half_rn((k < 128) ? t_out_w[n * 128 + k]
                                            : s_out_w[n * 128 + (k - 128)]);
    } else {
        int j = i - (2 * NW + 128 * 256);
        if (j < 384)      g_b[j] = t_in_b[j];
        else if (j < 768) g_b[j] = s_in_b[j - 384];
        else if (j < 896) g_ob[j - 768] = t_out_b[j - 768] + s_out_b[j - 768];
    }
}

// ---------------------------------------------------------------------------
// Projection GEMM (fp16): A resident [128][136]h, weight tiles double-buffered
// via cp.async ([128][136]h x2). Smem 102KB -> 2 CTAs/SM.
// 8 warps 2(m)x4(n), warp tile 64x32, m16n8k16.
// g_proj[m][c] = sum_k x[m][k] * g_w[c][k] + g_b[c]   (fp32 out)
// ---------------------------------------------------------------------------
#define AS_STR  68                       // A row stride in half2 (4B) units
#define PROJ_SMEM (3 * 128 * 136 * 2)

__global__ void __launch_bounds__(256, 2) tf32_gemm_proj(const float* __restrict__ A)
{
    extern __shared__ __half smh[];
    __half* As = smh;                    // [128][136]
    __half* Bb = smh + 128 * 136;        // 2 x [128][136]
    const uint32_t bbase = (uint32_t)__cvta_generic_to_shared(Bb);

    const int tid   = threadIdx.x;
    const int warp  = tid >> 5;
    const int lane  = tid & 31;
    const int group = lane >> 2;
    const int tg    = lane & 3;
    const int wm    = (warp & 1) * 64;
    const int wn    = (warp >> 1) * 32;

    const size_t arow0 = (size_t)blockIdx.x * 128;

    // ---- Load A tile once (fp32 -> fp16) ----
    {
        const int trow = tid >> 1;
        const int tcol = (tid & 1) * 64;
        const float* Ag = A + (arow0 + trow) * 128 + tcol;
        __half* Asp = As + trow * 136 + tcol;
        #pragma unroll
        for (int i = 0; i < 16; i++) {
            float4 a = *(const float4*)(Ag + i * 4);
            __half2* d = (__half2*)(Asp + i * 4);
            d[0] = __floats2half2_rn(a.x, a.y);
            d[1] = __floats2half2_rn(a.z, a.w);
        }
    }

    // ---- Weight tile prefetch (cp.async, 32KB per tile) ----
    auto prefB = [&](int nt) {
        uint32_t base = bbase + (nt & 1) * (128 * 136 * 2);
        #pragma unroll
        for (int i = 0; i < 8; i++) {
            int u   = i * 256 + tid;       // 0..2047
            int row = u >> 4;              // 0..127
            int c8  = u & 15;              // 16 x 8 halves per row
            cp16(base + row * 272 + c8 * 16,
                 g_w + (size_t)nt * 16384 + row * 128 + c8 * 8);
        }
        CP_COMMIT();
    };

    prefB(0);

    const uint32_t* As32 = (const uint32_t*)As;

    for (int nt = 0; nt < 6; nt++) {
        if (nt + 1 < 6) { prefB(nt + 1); CP_WAIT(1); }
        else            { CP_WAIT(0); }
        __syncthreads();

        const uint32_t* Bs32 = (const uint32_t*)(Bb + (nt & 1) * (128 * 136));

        float acc[4][4][4];
        #pragma unroll
        for (int mi = 0; mi < 4; mi++)
            #pragma unroll
            for (int ni = 0; ni < 4; ni++)
                #pragma unroll
                for (int r = 0; r < 4; r++) acc[mi][ni][r] = 0.f;

        #pragma unroll
        for (int k0 = 0; k0 < 128; k0 += 16) {
            const int kq = (k0 >> 1) + tg;     // half2 index within row
            uint32_t af[4][4];
            uint32_t bf[4][2];
            #pragma unroll
            for (int mi = 0; mi < 4; mi++) {
                int row = wm + mi * 16 + group;
                af[mi][0] = As32[row * AS_STR + kq];
                af[mi][1] = As32[(row + 8) * AS_STR + kq];
                af[mi][2] = As32[row * AS_STR + kq + 4];
                af[mi][3] = As32[(row + 8) * AS_STR + kq + 4];
            }
            #pragma unroll
            for (int ni = 0; ni < 4; ni++) {
                int row = wn + ni * 8 + group;
                bf[ni][0] = Bs32[row * AS_STR + kq];
                bf[ni][1] = Bs32[row * AS_STR + kq + 4];
            }
            #pragma unroll
            for (int mi = 0; mi < 4; mi++)
                #pragma unroll
                for (int ni = 0; ni < 4; ni++)
                    mma_f16(acc[mi][ni], af[mi], bf[ni]);
        }
        __syncthreads();   // reads of this buffer done before next-next prefetch

        // ---- Epilogue for weight tile nt (fp32 + bias) ----
        const int row0 = (int)arow0 + wm + group;
        const int col0 = wn + tg * 2;
        #pragma unroll
        for (int ni = 0; ni < 4; ni++) {
            int cc = col0 + ni * 8;
            int cg = nt * 128 + cc;
            float b0 = g_b[cg], b1 = g_b[cg + 1];
            #pragma unroll
            for (int mi = 0; mi < 4; mi++) {
                int r = row0 + mi * 16;
                *(float2*)&g_proj[(size_t)r * PROJW + cg] =
                    make_float2(acc[mi][ni][0] + b0, acc[mi][ni][1] + b1);
                *(float2*)&g_proj[(size_t)(r + 8) * PROJW + cg] =
                    make_float2(acc[mi][ni][2] + b0, acc[mi][ni][3] + b1);
            }
        }
    }
}

// ---------------------------------------------------------------------------
// Output GEMM (fp16): out = g_att(128000x256) @ g_wo^T + g_ob.
// Both operands fp16, cp.async double-buffered 64-half k-chunks.
// Smem 72KB -> 2 CTAs/SM.
// ---------------------------------------------------------------------------
#define OS_STR 36                        // chunk row stride in 4B units (72 halves)
#define OUT_SMEM (4 * 128 * 72 * 2)

__global__ void __launch_bounds__(256, 2) tf32_gemm_out(float* __restrict__ C)
{
    extern __shared__ __half smh[];
    __half* Ab = smh;                    // 2 x [128][72]
    __half* Bb = smh + 2 * 128 * 72;     // 2 x [128][72]
    const uint32_t abase = (uint32_t)__cvta_generic_to_shared(Ab);
    const uint32_t bbase = (uint32_t)__cvta_generic_to_shared(Bb);

    const int tid   = threadIdx.x;
    const int warp  = tid >> 5;
    const int lane  = tid & 31;
    const int group = lane >> 2;
    const int tg    = lane & 3;
    const int wm    = (warp & 1) * 64;
    const int wn    = (warp >> 1) * 32;

    const size_t arow0 = (size_t)blockIdx.x * 128;

    auto pref = [&](int c) {
        int kc = c * 64;
        uint32_t ab = abase + (c & 1) * (128 * 72 * 2);
        uint32_t bb = bbase + (c & 1) * (128 * 72 * 2);
        #pragma unroll
        for (int i = 0; i < 4; i++) {
            int u   = i * 256 + tid;       // 0..1023
            int row = u >> 3;              // 0..127
            int c8  = u & 7;               // 8 x 8 halves per row
            uint32_t off = row * 144 + c8 * 16;
            cp16(ab + off, g_att + (arow0 + row) * 256 + kc + c8 * 8);
            cp16(bb + off, g_wo + (size_t)row * 256 + kc + c8 * 8);
        }
        CP_COMMIT();
    };

    pref(0);

    float acc[4][4][4];
    #pragma unroll
    for (int mi = 0; mi < 4; mi++)
        #pragma unroll
        for (int ni = 0; ni < 4; ni++)
            #pragma unroll
            for (int r = 0; r < 4; r++) acc[mi][ni][r] = 0.f;

    for (int c = 0; c < 4; c++) {
        if (c + 1 < 4) { pref(c + 1); CP_WAIT(1); }
        else           { CP_WAIT(0); }
        __syncthreads();

        const uint32_t* As32 = (const uint32_t*)(Ab + (c & 1) * (128 * 72));
        const uint32_t* Bs32 = (const uint32_t*)(Bb + (c & 1) * (128 * 72));

        #pragma unroll
        for (int k0 = 0; k0 < 64; k0 += 16) {
            const int kq = (k0 >> 1) + tg;
            uint32_t af[4][4];
            uint32_t bf[4][2];
            #pragma unroll
            for (int mi = 0; mi < 4; mi++) {
                int row = wm + mi * 16 + group;
                af[mi][0] = As32[row * OS_STR + kq];
                af[mi][1] = As32[(row + 8) * OS_STR + kq];
                af[mi][2] = As32[row * OS_STR + kq + 4];
                af[mi][3] = As32[(row + 8) * OS_STR + kq + 4];
            }
            #pragma unroll
            for (int ni = 0; ni < 4; ni++) {
                int row = wn + ni * 8 + group;
                bf[ni][0] = Bs32[row * OS_STR + kq];
                bf[ni][1] = Bs32[row * OS_STR + kq + 4];
            }
            #pragma unroll
            for (int mi = 0; mi < 4; mi++)
                #pragma unroll
                for (int ni = 0; ni < 4; ni++)
                    mma_f16(acc[mi][ni], af[mi], bf[ni]);
        }
        __syncthreads();
    }

    const int row0 = (int)arow0 + wm + group;
    const int col0 = wn + tg * 2;
    #pragma unroll
    for (int ni = 0; ni < 4; ni++) {
        int c = col0 + ni * 8;
        float b0 = g_ob[c], b1 = g_ob[c + 1];
        #pragma unroll
        for (int mi = 0; mi < 4; mi++) {
            int r = row0 + mi * 16;
            *(float2*)&C[(size_t)r * 128 + c] =
                make_float2(acc[mi][ni][0] + b0, acc[mi][ni][1] + b1);
            *(float2*)&C[(size_t)(r + 8) * 128 + c] =
                make_float2(acc[mi][ni][2] + b0, acc[mi][ni][3] + b1);
        }
    }
}

// ---------------------------------------------------------------------------
// Merged attention: blocks [0,4000) temporal (block per (b,n)),
// blocks [4000,20000) spatial (warp per token). Independent work, disjoint
// outputs -> co-scheduled in one launch. Outputs written fp16 to g_att.
// ---------------------------------------------------------------------------
#define TEMP_STRIDE 388   // 384 + 4 pad (floats)
#define TEMP_SMEM   (32 * TEMP_STRIDE * 4)

__global__ void __launch_bounds__(256) attn_kernel(const int* __restrict__ route)
{
    extern __shared__ float S[];   // [32][TEMP_STRIDE] (temporal only)

    const int tid  = threadIdx.x;

    if (blockIdx.x < 4000) {
        // ---------------- temporal ----------------
        const int wid  = tid >> 5;     // head
        const int lane = tid & 31;     // l
        const int n = blockIdx.x % N_;
        const int b = blockIdx.x / N_;

        #pragma unroll
        for (int i = 0; i < 12; i++) {
            int fid = i * 256 + tid;
            int r   = fid / 96;
            int c4  = fid % 96;
            size_t m = ((size_t)r * B_ + b) * N_ + n;
            float4 v = *(const float4*)(g_proj + m * PROJW + c4 * 4);
            *(float4*)(S + r * TEMP_STRIDE + c4 * 4) = v;
        }
        __syncthreads();

        const int hoff = wid * DH_;
        float4 q[4];
        #pragma unroll
        for (int i = 0; i < 4; i++)
            q[i] = *(const float4*)(S + lane * TEMP_STRIDE + hoff + i * 4);

        float s[32];
        #pragma unroll
        for (int mm = 0; mm < 32; mm++) {
            const float* kr = S + mm * TEMP_STRIDE + 128 + hoff;
            float a = 0.f;
            #pragma unroll
            for (int i = 0; i < 4; i++) {
                float4 kv = *(const float4*)(kr + i * 4);   // broadcast
                a += q[i].x * kv.x + q[i].y * kv.y + q[i].z * kv.z + q[i].w * kv.w;
            }
            s[mm] = a * 0.25f;
        }

        float mx = s[0];
        #pragma unroll
        for (int mm = 1; mm < 32; mm++) mx = fmaxf(mx, s[mm]);
        float sum = 0.f;
        #pragma unroll
        for (int mm = 0; mm < 32; mm++) { s[mm] = __expf(s[mm] - mx); sum += s[mm]; }
        float inv = 1.f / sum;

        float4 o[4];
        #pragma unroll
        for (int i = 0; i < 4; i++) o[i] = make_float4(0.f, 0.f, 0.f, 0.f);
        #pragma unroll
        for (int mm = 0; mm < 32; mm++) {
            float p = s[mm] * inv;
            const float* vr = S + mm * TEMP_STRIDE + 256 + hoff;
            #pragma unroll
            for (int i = 0; i < 4; i++) {
                float4 vv = *(const float4*)(vr + i * 4);   // broadcast
                o[i].x += p * vv.x; o[i].y += p * vv.y;
                o[i].z += p * vv.z; o[i].w += p * vv.w;
            }
        }

        size_t m = ((size_t)lane * B_ + b) * N_ + n;
        __half2* orow = (__half2*)(g_att + m * 256 + hoff);
        #pragma unroll
        for (int i = 0; i < 4; i++) {
            orow[i * 2]     = __floats2half2_rn(o[i].x, o[i].y);
            orow[i * 2 + 1] = __floats2half2_rn(o[i].z, o[i].w);
        }
    } else {
        // ---------------- spatial (register-only) ----------------
        const int w    = tid >> 5;
        const int lane = tid & 31;
        const size_t m = (size_t)(blockIdx.x - 4000) * 8 + w;
        const int n    = (int)(m % N_);
        const size_t lbbase = m - n;               // row of (l, b, 0)

        float4 q4 = *(const float4*)(g_proj + m * PROJW + 384 + lane * 4);

        int nbv = (lane < 8) ? route[n * 8 + lane] : 0;

        float s[8];
        float4 v4[8];
        #pragma unroll
        for (int kk = 0; kk < 8; kk++) {
            int nb = __shfl_sync(0xffffffffu, nbv, kk);
            const float* r = g_proj + (lbbase + nb) * PROJW;
            float4 k4 = *(const float4*)(r + 512 + lane * 4);
            v4[kk]    = *(const float4*)(r + 640 + lane * 4);
            float part = q4.x * k4.x + q4.y * k4.y + q4.z * k4.z + q4.w * k4.w;
            part += __shfl_xor_sync(0xffffffffu, part, 1);
            part += __shfl_xor_sync(0xffffffffu, part, 2);
            s[kk] = part * 0.25f;
        }

        float mx = s[0];
        #pragma unroll
        for (int kk = 1; kk < 8; kk++) mx = fmaxf(mx, s[kk]);
        float sum = 0.f;
        #pragma unroll
        for (int kk = 0; kk < 8; kk++) { s[kk] = __expf(s[kk] - mx); sum += s[kk]; }
        float inv = 1.f / sum;

        float4 o = make_float4(0.f, 0.f, 0.f, 0.f);
        #pragma unroll
        for (int kk = 0; kk < 8; kk++) {
            float pb = s[kk] * inv;
            o.x += pb * v4[kk].x; o.y += pb * v4[kk].y;
            o.z += pb * v4[kk].z; o.w += pb * v4[kk].w;
        }
        __half2* dst = (__half2*)(g_att + m * 256 + 128 + lane * 4);
        dst[0] = __floats2half2_rn(o.x, o.y);
        dst[1] = __floats2half2_rn(o.z, o.w);
    }
}

// ---------------------------------------------------------------------------
extern "C" void kernel_launch(void* const* d_in, const int* in_sizes, int n_in,
                              void* d_out, int out_size)
{
    const float* x       = (const float*)d_in[0];
    const int*   route   = (const int*)  d_in[1];
    const float* t_in_w  = (const float*)d_in[2];
    const float* t_in_b  = (const float*)d_in[3];
    const float* t_out_w = (const float*)d_in[4];
    const float* t_out_b = (const float*)d_in[5];
    const float* s_in_w  = (const float*)d_in[6];
    const float* s_in_b  = (const float*)d_in[7];
    const float* s_out_w = (const float*)d_in[8];
    const float* s_out_b = (const float*)d_in[9];
    float* out = (float*)d_out;

    cudaFuncSetAttribute(tf32_gemm_proj, cudaFuncAttributeMaxDynamicSharedMemorySize, PROJ_SMEM);
    cudaFuncSetAttribute(tf32_gemm_out,  cudaFuncAttributeMaxDynamicSharedMemorySize, OUT_SMEM);
    cudaFuncSetAttribute(attn_kernel,    cudaFuncAttributeMaxDynamicSharedMemorySize, TEMP_SMEM);

    // 1) pack weights (fp16)
    prep_weights<<<516, 256>>>(t_in_w, t_in_b, s_in_w, s_in_b,
                               t_out_w, t_out_b, s_out_w, s_out_b);

    // 2) fused projection: x(128000x128) @ g_w^T + g_b -> g_proj (fp32)
    tf32_gemm_proj<<<M_ / 128, 256, PROJ_SMEM>>>(x);

    // 3) merged temporal + spatial attention -> g_att (fp16)
    attn_kernel<<<4000 + M_ / 8, 256, TEMP_SMEM>>>(route);

    // 4) out = g_att @ g_wo^T + g_ob
    tf32_gemm_out<<<M_ / 128, 256, OUT_SMEM>>>(out);
}

// round 16
// speedup vs baseline: 2.2145x; 1.0252x over previous
#include <cuda_runtime.h>
#include <cuda_fp16.h>
#include <math.h>
#include <stdint.h>

// Problem constants
#define L_   32
#define B_   4
#define N_   1000
#define D_   128
#define K_   8
#define H_   8
#define DH_  16
#define M_   (L_ * B_ * N_)   // 128000 tokens
#define PROJW 768             // q|k|v|sq|sk|sv concatenated per token

// Scratch (device globals: allocation-free, graph-capturable)
__device__ __half g_proj[(size_t)M_ * PROJW];  // ~196 MB fp16 (attn converts to fp32)
__device__ __half g_att [(size_t)M_ * 256];    // [o | so] fp16 (GEMM input)
__device__ __half g_w   [PROJW * 128];         // concat in-weights fp16
__device__ __half g_wo  [128 * 256];           // concat out-weights fp16
__device__ float  g_b   [PROJW];               // concat in-biases (fp32)
__device__ float  g_ob  [128];                 // t_out_b + s_out_b (fp32)

// ---------------------------------------------------------------------------
// Helpers
// ---------------------------------------------------------------------------
__device__ __forceinline__ void mma_f16(float* d, const uint32_t* a, const uint32_t* b)
{
    asm volatile(
        "mma.sync.aligned.m16n8k16.row.col.f32.f16.f16.f32 "
        "{%0,%1,%2,%3}, {%4,%5,%6,%7}, {%8,%9}, {%0,%1,%2,%3};"
        : "+f"(d[0]), "+f"(d[1]), "+f"(d[2]), "+f"(d[3])
        : "r"(a[0]), "r"(a[1]), "r"(a[2]), "r"(a[3]), "r"(b[0]), "r"(b[1]));
}

__device__ __forceinline__ void cp16(uint32_t dst_smem, const void* src)
{
    asm volatile("cp.async.ca.shared.global [%0], [%1], 16;" :: "r"(dst_smem), "l"(src));
}
#define CP_COMMIT()  asm volatile("cp.async.commit_group;")
#define CP_WAIT(n)   asm volatile("cp.async.wait_group %0;" :: "n"(n))

__device__ __forceinline__ float4 h4_to_f4(uint2 u)
{
    float2 a = __half22float2(*(__half2*)&u.x);
    float2 b = __half22float2(*(__half2*)&u.y);
    return make_float4(a.x, a.y, b.x, b.y);
}

// ---------------------------------------------------------------------------
// Pack weights/biases (fp16 — same 10-bit mantissa as tf32)
// ---------------------------------------------------------------------------
__global__ void prep_weights(const float* __restrict__ t_in_w,
                             const float* __restrict__ t_in_b,
                             const float* __restrict__ s_in_w,
                             const float* __restrict__ s_in_b,
                             const float* __restrict__ t_out_w,
                             const float* __restrict__ t_out_b,
                             const float* __restrict__ s_out_w,
                             const float* __restrict__ s_out_b)
{
    int i = blockIdx.x * 256 + threadIdx.x;
    const int NW = 384 * 128;                 // 49152
    if (i < NW) {
        g_w[i] = __float2half_rn(t_in_w[i]);
    } else if (i < 2 * NW) {
        g_w[i] = __float2half_rn(s_in_w[i - NW]);
    } else if (i < 2 * NW + 128 * 256) {
        int j = i - 2 * NW;
        int n = j >> 8;
        int k = j & 255;
        g_wo[j] = __float2half_rn((k < 128) ? t_out_w[n * 128 + k]
                                            : s_out_w[n * 128 + (k - 128)]);
    } else {
        int j = i - (2 * NW + 128 * 256);
        if (j < 384)      g_b[j] = t_in_b[j];
        else if (j < 768) g_b[j] = s_in_b[j - 384];
        else if (j < 896) g_ob[j - 768] = t_out_b[j - 768] + s_out_b[j - 768];
    }
}

// ---------------------------------------------------------------------------
// Projection GEMM (fp16): A resident [128][136]h, weight tiles double-buffered
// via cp.async. Smem 102KB -> 2 CTAs/SM. 8 warps 2(m)x4(n), m16n8k16.
// g_proj[m][c] = fp16( sum_k x[m][k]*g_w[c][k] + g_b[c] )
// ---------------------------------------------------------------------------
#define AS_STR  68                       // A row stride in half2 (4B) units
#define PROJ_SMEM (3 * 128 * 136 * 2)

__global__ void __launch_bounds__(256, 2) gemm_proj(const float* __restrict__ A)
{
    extern __shared__ __half smh[];
    __half* As = smh;                    // [128][136]
    __half* Bb = smh + 128 * 136;        // 2 x [128][136]
    const uint32_t bbase = (uint32_t)__cvta_generic_to_shared(Bb);

    const int tid   = threadIdx.x;
    const int warp  = tid >> 5;
    const int lane  = tid & 31;
    const int group = lane >> 2;
    const int tg    = lane & 3;
    const int wm    = (warp & 1) * 64;
    const int wn    = (warp >> 1) * 32;

    const size_t arow0 = (size_t)blockIdx.x * 128;

    // ---- Load A tile once (fp32 -> fp16) ----
    {
        const int trow = tid >> 1;
        const int tcol = (tid & 1) * 64;
        const float* Ag = A + (arow0 + trow) * 128 + tcol;
        __half* Asp = As + trow * 136 + tcol;
        #pragma unroll
        for (int i = 0; i < 16; i++) {
            float4 a = *(const float4*)(Ag + i * 4);
            __half2* d = (__half2*)(Asp + i * 4);
            d[0] = __floats2half2_rn(a.x, a.y);
            d[1] = __floats2half2_rn(a.z, a.w);
        }
    }

    // ---- Weight tile prefetch (cp.async, 32KB per tile) ----
    auto prefB = [&](int nt) {
        uint32_t base = bbase + (nt & 1) * (128 * 136 * 2);
        #pragma unroll
        for (int i = 0; i < 8; i++) {
            int u   = i * 256 + tid;       // 0..2047
            int row = u >> 4;              // 0..127
            int c8  = u & 15;              // 16 x 8 halves per row
            cp16(base + row * 272 + c8 * 16,
                 g_w + (size_t)nt * 16384 + row * 128 + c8 * 8);
        }
        CP_COMMIT();
    };

    prefB(0);

    const uint32_t* As32 = (const uint32_t*)As;

    for (int nt = 0; nt < 6; nt++) {
        if (nt + 1 < 6) { prefB(nt + 1); CP_WAIT(1); }
        else            { CP_WAIT(0); }
        __syncthreads();

        const uint32_t* Bs32 = (const uint32_t*)(Bb + (nt & 1) * (128 * 136));

        float acc[4][4][4];
        #pragma unroll
        for (int mi = 0; mi < 4; mi++)
            #pragma unroll
            for (int ni = 0; ni < 4; ni++)
                #pragma unroll
                for (int r = 0; r < 4; r++) acc[mi][ni][r] = 0.f;

        #pragma unroll
        for (int k0 = 0; k0 < 128; k0 += 16) {
            const int kq = (k0 >> 1) + tg;     // half2 index within row
            uint32_t af[4][4];
            uint32_t bf[4][2];
            #pragma unroll
            for (int mi = 0; mi < 4; mi++) {
                int row = wm + mi * 16 + group;
                af[mi][0] = As32[row * AS_STR + kq];
                af[mi][1] = As32[(row + 8) * AS_STR + kq];
                af[mi][2] = As32[row * AS_STR + kq + 4];
                af[mi][3] = As32[(row + 8) * AS_STR + kq + 4];
            }
            #pragma unroll
            for (int ni = 0; ni < 4; ni++) {
                int row = wn + ni * 8 + group;
                bf[ni][0] = Bs32[row * AS_STR + kq];
                bf[ni][1] = Bs32[row * AS_STR + kq + 4];
            }
            #pragma unroll
            for (int mi = 0; mi < 4; mi++)
                #pragma unroll
                for (int ni = 0; ni < 4; ni++)
                    mma_f16(acc[mi][ni], af[mi], bf[ni]);
        }
        __syncthreads();

        // ---- Epilogue for weight tile nt (bias, store fp16) ----
        const int row0 = (int)arow0 + wm + group;
        const int col0 = wn + tg * 2;
        #pragma unroll
        for (int ni = 0; ni < 4; ni++) {
            int cc = col0 + ni * 8;
            int cg = nt * 128 + cc;
            float b0 = g_b[cg], b1 = g_b[cg + 1];
            #pragma unroll
            for (int mi = 0; mi < 4; mi++) {
                int r = row0 + mi * 16;
                *(__half2*)&g_proj[(size_t)r * PROJW + cg] =
                    __floats2half2_rn(acc[mi][ni][0] + b0, acc[mi][ni][1] + b1);
                *(__half2*)&g_proj[(size_t)(r + 8) * PROJW + cg] =
                    __floats2half2_rn(acc[mi][ni][2] + b0, acc[mi][ni][3] + b1);
            }
        }
    }
}

// ---------------------------------------------------------------------------
// Output GEMM (fp16): out = g_att(128000x256) @ g_wo^T + g_ob.
// cp.async double-buffered 64-half k-chunks. Smem 72KB -> 2 CTAs/SM.
// ---------------------------------------------------------------------------
#define OS_STR 36                        // chunk row stride in 4B units (72 halves)
#define OUT_SMEM (4 * 128 * 72 * 2)

__global__ void __launch_bounds__(256, 2) gemm_out(float* __restrict__ C)
{
    extern __shared__ __half smh[];
    __half* Ab = smh;                    // 2 x [128][72]
    __half* Bb = smh + 2 * 128 * 72;     // 2 x [128][72]
    const uint32_t abase = (uint32_t)__cvta_generic_to_shared(Ab);
    const uint32_t bbase = (uint32_t)__cvta_generic_to_shared(Bb);

    const int tid   = threadIdx.x;
    const int warp  = tid >> 5;
    const int lane  = tid & 31;
    const int group = lane >> 2;
    const int tg    = lane & 3;
    const int wm    = (warp & 1) * 64;
    const int wn    = (warp >> 1) * 32;

    const size_t arow0 = (size_t)blockIdx.x * 128;

    auto pref = [&](int c) {
        int kc = c * 64;
        uint32_t ab = abase + (c & 1) * (128 * 72 * 2);
        uint32_t bb = bbase + (c & 1) * (128 * 72 * 2);
        #pragma unroll
        for (int i = 0; i < 4; i++) {
            int u   = i * 256 + tid;       // 0..1023
            int row = u >> 3;              // 0..127
            int c8  = u & 7;               // 8 x 8 halves per row
            uint32_t off = row * 144 + c8 * 16;
            cp16(ab + off, g_att + (arow0 + row) * 256 + kc + c8 * 8);
            cp16(bb + off, g_wo + (size_t)row * 256 + kc + c8 * 8);
        }
        CP_COMMIT();
    };

    pref(0);

    float acc[4][4][4];
    #pragma unroll
    for (int mi = 0; mi < 4; mi++)
        #pragma unroll
        for (int ni = 0; ni < 4; ni++)
            #pragma unroll
            for (int r = 0; r < 4; r++) acc[mi][ni][r] = 0.f;

    for (int c = 0; c < 4; c++) {
        if (c + 1 < 4) { pref(c + 1); CP_WAIT(1); }
        else           { CP_WAIT(0); }
        __syncthreads();

        const uint32_t* As32 = (const uint32_t*)(Ab + (c & 1) * (128 * 72));
        const uint32_t* Bs32 = (const uint32_t*)(Bb + (c & 1) * (128 * 72));

        #pragma unroll
        for (int k0 = 0; k0 < 64; k0 += 16) {
            const int kq = (k0 >> 1) + tg;
            uint32_t af[4][4];
            uint32_t bf[4][2];
            #pragma unroll
            for (int mi = 0; mi < 4; mi++) {
                int row = wm + mi * 16 + group;
                af[mi][0] = As32[row * OS_STR + kq];
                af[mi][1] = As32[(row + 8) * OS_STR + kq];
                af[mi][2] = As32[row * OS_STR + kq + 4];
                af[mi][3] = As32[(row + 8) * OS_STR + kq + 4];
            }
            #pragma unroll
            for (int ni = 0; ni < 4; ni++) {
                int row = wn + ni * 8 + group;
                bf[ni][0] = Bs32[row * OS_STR + kq];
                bf[ni][1] = Bs32[row * OS_STR + kq + 4];
            }
            #pragma unroll
            for (int mi = 0; mi < 4; mi++)
                #pragma unroll
                for (int ni = 0; ni < 4; ni++)
                    mma_f16(acc[mi][ni], af[mi], bf[ni]);
        }
        __syncthreads();
    }

    const int row0 = (int)arow0 + wm + group;
    const int col0 = wn + tg * 2;
    #pragma unroll
    for (int ni = 0; ni < 4; ni++) {
        int c = col0 + ni * 8;
        float b0 = g_ob[c], b1 = g_ob[c + 1];
        #pragma unroll
        for (int mi = 0; mi < 4; mi++) {
            int r = row0 + mi * 16;
            *(float2*)&C[(size_t)r * 128 + c] =
                make_float2(acc[mi][ni][0] + b0, acc[mi][ni][1] + b1);
            *(float2*)&C[(size_t)(r + 8) * 128 + c] =
                make_float2(acc[mi][ni][2] + b0, acc[mi][ni][3] + b1);
        }
    }
}

// ---------------------------------------------------------------------------
// Merged attention: blocks [0,4000) temporal (block per (b,n)),
// blocks [4000,20000) spatial (warp per token). g_proj is fp16; convert to
// fp32 for the math. Outputs fp16 -> g_att.
// ---------------------------------------------------------------------------
#define TEMP_STRIDE 388   // 384 + 4 pad (floats)
#define TEMP_SMEM   (32 * TEMP_STRIDE * 4)

__global__ void __launch_bounds__(256) attn_kernel(const int* __restrict__ route)
{
    extern __shared__ float S[];   // [32][TEMP_STRIDE] fp32 (temporal only)

    const int tid  = threadIdx.x;

    if (blockIdx.x < 4000) {
        // ---------------- temporal ----------------
        const int wid  = tid >> 5;     // head
        const int lane = tid & 31;     // l
        const int n = blockIdx.x % N_;
        const int b = blockIdx.x / N_;

        // Coalesced load: 32 rows x 384 halves (48 x uint4 per row), cvt->fp32
        #pragma unroll
        for (int i = 0; i < 6; i++) {
            int fid = i * 256 + tid;       // 0..1535
            int r   = fid / 48;
            int c8  = fid % 48;
            size_t m = ((size_t)r * B_ + b) * N_ + n;
            uint4 v = *(const uint4*)(g_proj + m * PROJW + c8 * 8);
            float* d = S + r * TEMP_STRIDE + c8 * 8;
            float2 f0 = __half22float2(*(__half2*)&v.x);
            float2 f1 = __half22float2(*(__half2*)&v.y);
            float2 f2 = __half22float2(*(__half2*)&v.z);
            float2 f3 = __half22float2(*(__half2*)&v.w);
            d[0] = f0.x; d[1] = f0.y; d[2] = f1.x; d[3] = f1.y;
            d[4] = f2.x; d[5] = f2.y; d[6] = f3.x; d[7] = f3.y;
        }
        __syncthreads();

        const int hoff = wid * DH_;
        float4 q[4];
        #pragma unroll
        for (int i = 0; i < 4; i++)
            q[i] = *(const float4*)(S + lane * TEMP_STRIDE + hoff + i * 4);

        float s[32];
        #pragma unroll
        for (int mm = 0; mm < 32; mm++) {
            const float* kr = S + mm * TEMP_STRIDE + 128 + hoff;
            float a = 0.f;
            #pragma unroll
            for (int i = 0; i < 4; i++) {
                float4 kv = *(const float4*)(kr + i * 4);   // broadcast
                a += q[i].x * kv.x + q[i].y * kv.y + q[i].z * kv.z + q[i].w * kv.w;
            }
            s[mm] = a * 0.25f;
        }

        float mx = s[0];
        #pragma unroll
        for (int mm = 1; mm < 32; mm++) mx = fmaxf(mx, s[mm]);
        float sum = 0.f;
        #pragma unroll
        for (int mm = 0; mm < 32; mm++) { s[mm] = __expf(s[mm] - mx); sum += s[mm]; }
        float inv = 1.f / sum;

        float4 o[4];
        #pragma unroll
        for (int i = 0; i < 4; i++) o[i] = make_float4(0.f, 0.f, 0.f, 0.f);
        #pragma unroll
        for (int mm = 0; mm < 32; mm++) {
            float p = s[mm] * inv;
            const float* vr = S + mm * TEMP_STRIDE + 256 + hoff;
            #pragma unroll
            for (int i = 0; i < 4; i++) {
                float4 vv = *(const float4*)(vr + i * 4);   // broadcast
                o[i].x += p * vv.x; o[i].y += p * vv.y;
                o[i].z += p * vv.z; o[i].w += p * vv.w;
            }
        }

        size_t m = ((size_t)lane * B_ + b) * N_ + n;
        __half2* orow = (__half2*)(g_att + m * 256 + hoff);
        #pragma unroll
        for (int i = 0; i < 4; i++) {
            orow[i * 2]     = __floats2half2_rn(o[i].x, o[i].y);
            orow[i * 2 + 1] = __floats2half2_rn(o[i].z, o[i].w);
        }
    } else {
        // ---------------- spatial (register-only) ----------------
        const int w    = tid >> 5;
        const int lane = tid & 31;
        const size_t m = (size_t)(blockIdx.x - 4000) * 8 + w;
        const int n    = (int)(m % N_);
        const size_t lbbase = m - n;               // row of (l, b, 0)

        float4 q4 = h4_to_f4(*(const uint2*)(g_proj + m * PROJW + 384 + lane * 4));

        int nbv = (lane < 8) ? route[n * 8 + lane] : 0;

        float s[8];
        float4 v4[8];
        #pragma unroll
        for (int kk = 0; kk < 8; kk++) {
            int nb = __shfl_sync(0xffffffffu, nbv, kk);
            const __half* r = g_proj + (lbbase + nb) * PROJW;
            float4 k4 = h4_to_f4(*(const uint2*)(r + 512 + lane * 4));
            v4[kk]    = h4_to_f4(*(const uint2*)(r + 640 + lane * 4));
            float part = q4.x * k4.x + q4.y * k4.y + q4.z * k4.z + q4.w * k4.w;
            part += __shfl_xor_sync(0xffffffffu, part, 1);
            part += __shfl_xor_sync(0xffffffffu, part, 2);
            s[kk] = part * 0.25f;
        }

        float mx = s[0];
        #pragma unroll
        for (int kk = 1; kk < 8; kk++) mx = fmaxf(mx, s[kk]);
        float sum = 0.f;
        #pragma unroll
        for (int kk = 0; kk < 8; kk++) { s[kk] = __expf(s[kk] - mx); sum += s[kk]; }
        float inv = 1.f / sum;

        float4 o = make_float4(0.f, 0.f, 0.f, 0.f);
        #pragma unroll
        for (int kk = 0; kk < 8; kk++) {
            float pb = s[kk] * inv;
            o.x += pb * v4[kk].x; o.y += pb * v4[kk].y;
            o.z += pb * v4[kk].z; o.w += pb * v4[kk].w;
        }
        __half2* dst = (__half2*)(g_att + m * 256 + 128 + lane * 4);
        dst[0] = __floats2half2_rn(o.x, o.y);
        dst[1] = __floats2half2_rn(o.z, o.w);
    }
}

// ---------------------------------------------------------------------------
extern "C" void kernel_launch(void* const* d_in, const int* in_sizes, int n_in,
                              void* d_out, int out_size)
{
    const float* x       = (const float*)d_in[0];
    const int*   route   = (const int*)  d_in[1];
    const float* t_in_w  = (const float*)d_in[2];
    const float* t_in_b  = (const float*)d_in[3];
    const float* t_out_w = (const float*)d_in[4];
    const float* t_out_b = (const float*)d_in[5];
    const float* s_in_w  = (const float*)d_in[6];
    const float* s_in_b  = (const float*)d_in[7];
    const float* s_out_w = (const float*)d_in[8];
    const float* s_out_b = (const float*)d_in[9];
    float* out = (float*)d_out;

    cudaFuncSetAttribute(gemm_proj,   cudaFuncAttributeMaxDynamicSharedMemorySize, PROJ_SMEM);
    cudaFuncSetAttribute(gemm_out,    cudaFuncAttributeMaxDynamicSharedMemorySize, OUT_SMEM);
    cudaFuncSetAttribute(attn_kernel, cudaFuncAttributeMaxDynamicSharedMemorySize, TEMP_SMEM);

    // 1) pack weights (fp16)
    prep_weights<<<516, 256>>>(t_in_w, t_in_b, s_in_w, s_in_b,
                               t_out_w, t_out_b, s_out_w, s_out_b);

    // 2) fused projection: x(128000x128) @ g_w^T + g_b -> g_proj (fp16)
    gemm_proj<<<M_ / 128, 256, PROJ_SMEM>>>(x);

    // 3) merged temporal + spatial attention -> g_att (fp16)
    attn_kernel<<<4000 + M_ / 8, 256, TEMP_SMEM>>>(route);

    // 4) out = g_att @ g_wo^T + g_ob
    gemm_out<<<M_ / 128, 256, OUT_SMEM>>>(out);
}

// round 17
// speedup vs baseline: 2.2744x; 1.0271x over previous
#include <cuda_runtime.h>
#include <cuda_fp16.h>
#include <math.h>
#include <stdint.h>

// Problem constants
#define L_   32
#define B_   4
#define N_   1000
#define D_   128
#define K_   8
#define H_   8
#define DH_  16
#define M_   (L_ * B_ * N_)   // 128000 tokens
#define PROJW 768             // q|k|v|sq|sk|sv concatenated per token

// Scratch (device globals: allocation-free, graph-capturable)
__device__ __half g_proj[(size_t)M_ * PROJW];  // ~196 MB fp16
__device__ __half g_att [(size_t)M_ * 256];    // [o | so] fp16 (GEMM input)
__device__ __half g_w   [PROJW * 128];         // concat in-weights fp16
__device__ __half g_wo  [128 * 256];           // concat out-weights fp16
__device__ float  g_b   [PROJW];               // concat in-biases (fp32)
__device__ float  g_ob  [128];                 // t_out_b + s_out_b (fp32)

// ---------------------------------------------------------------------------
// Helpers
// ---------------------------------------------------------------------------
__device__ __forceinline__ void mma_f16(float* d, const uint32_t* a, const uint32_t* b)
{
    asm volatile(
        "mma.sync.aligned.m16n8k16.row.col.f32.f16.f16.f32 "
        "{%0,%1,%2,%3}, {%4,%5,%6,%7}, {%8,%9}, {%0,%1,%2,%3};"
        : "+f"(d[0]), "+f"(d[1]), "+f"(d[2]), "+f"(d[3])
        : "r"(a[0]), "r"(a[1]), "r"(a[2]), "r"(a[3]), "r"(b[0]), "r"(b[1]));
}

__device__ __forceinline__ void ldsm_x4(uint32_t& r0, uint32_t& r1,
                                        uint32_t& r2, uint32_t& r3, uint32_t addr)
{
    asm volatile("ldmatrix.sync.aligned.m8n8.x4.shared.b16 {%0,%1,%2,%3}, [%4];"
                 : "=r"(r0), "=r"(r1), "=r"(r2), "=r"(r3) : "r"(addr));
}

__device__ __forceinline__ void cp16(uint32_t dst_smem, const void* src)
{
    asm volatile("cp.async.ca.shared.global [%0], [%1], 16;" :: "r"(dst_smem), "l"(src));
}
#define CP_COMMIT()  asm volatile("cp.async.commit_group;")
#define CP_WAIT(n)   asm volatile("cp.async.wait_group %0;" :: "n"(n))

__device__ __forceinline__ float4 h4_to_f4(uint2 u)
{
    float2 a = __half22float2(*(__half2*)&u.x);
    float2 b = __half22float2(*(__half2*)&u.y);
    return make_float4(a.x, a.y, b.x, b.y);
}

// ---------------------------------------------------------------------------
// Pack weights/biases (fp16)
// ---------------------------------------------------------------------------
__global__ void prep_weights(const float* __restrict__ t_in_w,
                             const float* __restrict__ t_in_b,
                             const float* __restrict__ s_in_w,
                             const float* __restrict__ s_in_b,
                             const float* __restrict__ t_out_w,
                             const float* __restrict__ t_out_b,
                             const float* __restrict__ s_out_w,
                             const float* __restrict__ s_out_b)
{
    int i = blockIdx.x * 256 + threadIdx.x;
    const int NW = 384 * 128;                 // 49152
    if (i < NW) {
        g_w[i] = __float2half_rn(t_in_w[i]);
    } else if (i < 2 * NW) {
        g_w[i] = __float2half_rn(s_in_w[i - NW]);
    } else if (i < 2 * NW + 128 * 256) {
        int j = i - 2 * NW;
        int n = j >> 8;
        int k = j & 255;
        g_wo[j] = __float2half_rn((k < 128) ? t_out_w[n * 128 + k]
                                            : s_out_w[n * 128 + (k - 128)]);
    } else {
        int j = i - (2 * NW + 128 * 256);
        if (j < 384)      g_b[j] = t_in_b[j];
        else if (j < 768) g_b[j] = s_in_b[j - 384];
        else if (j < 896) g_ob[j - 768] = t_out_b[j - 768] + s_out_b[j - 768];
    }
}

// ---------------------------------------------------------------------------
// Projection GEMM (fp16, ldmatrix): A resident [128][136]h, weight tiles
// double-buffered via cp.async. Smem 102KB -> 2 CTAs/SM. 8 warps 2(m)x4(n).
// ---------------------------------------------------------------------------
#define PROJ_SMEM (3 * 128 * 136 * 2)

__global__ void __launch_bounds__(256, 2) gemm_proj(const float* __restrict__ A)
{
    extern __shared__ __half smh[];
    __half* As = smh;                    // [128][136]
    __half* Bb = smh + 128 * 136;        // 2 x [128][136]
    const uint32_t as_u = (uint32_t)__cvta_generic_to_shared(As);
    const uint32_t bb_u = (uint32_t)__cvta_generic_to_shared(Bb);

    const int tid   = threadIdx.x;
    const int warp  = tid >> 5;
    const int lane  = tid & 31;
    const int group = lane >> 2;
    const int tg    = lane & 3;
    const int wm    = (warp & 1) * 64;
    const int wn    = (warp >> 1) * 32;

    const size_t arow0 = (size_t)blockIdx.x * 128;

    // ---- Load A tile once (fp32 -> fp16) ----
    {
        const int trow = tid >> 1;
        const int tcol = (tid & 1) * 64;
        const float* Ag = A + (arow0 + trow) * 128 + tcol;
        __half* Asp = As + trow * 136 + tcol;
        #pragma unroll
        for (int i = 0; i < 16; i++) {
            float4 a = *(const float4*)(Ag + i * 4);
            __half2* d = (__half2*)(Asp + i * 4);
            d[0] = __floats2half2_rn(a.x, a.y);
            d[1] = __floats2half2_rn(a.z, a.w);
        }
    }

    // ---- Weight tile prefetch (cp.async, 32KB per tile) ----
    auto prefB = [&](int nt) {
        uint32_t base = bb_u + (nt & 1) * (128 * 136 * 2);
        #pragma unroll
        for (int i = 0; i < 8; i++) {
            int u   = i * 256 + tid;       // 0..2047
            int row = u >> 4;              // 0..127
            int c8  = u & 15;              // 16 x 8 halves per row
            cp16(base + row * 272 + c8 * 16,
                 g_w + (size_t)nt * 16384 + row * 128 + c8 * 8);
        }
        CP_COMMIT();
    };

    prefB(0);

    // ldmatrix base addresses (bytes)
    // A: row = wm + (lane&15), col-half offset (lane>>4)*8; +mi*16 rows; +k0 halves
    const uint32_t a_base =
        as_u + (((wm + (lane & 15)) * 136 + ((lane >> 4) << 3)) << 1);
    // B: row = wn + (lane&7) + ((lane&16)?8:0), col ((lane&8)?8:0); +pair*16 rows
    const uint32_t b_off =
        (((wn + (lane & 7) + ((lane & 16) ? 8 : 0)) * 136 + ((lane & 8) ? 8 : 0)) << 1);

    for (int nt = 0; nt < 6; nt++) {
        if (nt + 1 < 6) { prefB(nt + 1); CP_WAIT(1); }
        else            { CP_WAIT(0); }
        __syncthreads();

        const uint32_t b_cur = bb_u + (nt & 1) * (128 * 136 * 2) + b_off;

        float acc[4][4][4];
        #pragma unroll
        for (int mi = 0; mi < 4; mi++)
            #pragma unroll
            for (int ni = 0; ni < 4; ni++)
                #pragma unroll
                for (int r = 0; r < 4; r++) acc[mi][ni][r] = 0.f;

        #pragma unroll
        for (int k0 = 0; k0 < 128; k0 += 16) {
            uint32_t af[4][4];
            uint32_t bf[4][2];
            #pragma unroll
            for (int mi = 0; mi < 4; mi++)
                ldsm_x4(af[mi][0], af[mi][1], af[mi][2], af[mi][3],
                        a_base + mi * (16 * 136 * 2) + k0 * 2);
            ldsm_x4(bf[0][0], bf[0][1], bf[1][0], bf[1][1], b_cur + k0 * 2);
            ldsm_x4(bf[2][0], bf[2][1], bf[3][0], bf[3][1],
                    b_cur + (16 * 136 * 2) + k0 * 2);
            #pragma unroll
            for (int mi = 0; mi < 4; mi++)
                #pragma unroll
                for (int ni = 0; ni < 4; ni++)
                    mma_f16(acc[mi][ni], af[mi], bf[ni]);
        }
        __syncthreads();

        // ---- Epilogue (bias, store fp16) ----
        const int row0 = (int)arow0 + wm + group;
        const int col0 = wn + tg * 2;
        #pragma unroll
        for (int ni = 0; ni < 4; ni++) {
            int cc = col0 + ni * 8;
            int cg = nt * 128 + cc;
            float b0 = g_b[cg], b1 = g_b[cg + 1];
            #pragma unroll
            for (int mi = 0; mi < 4; mi++) {
                int r = row0 + mi * 16;
                *(__half2*)&g_proj[(size_t)r * PROJW + cg] =
                    __floats2half2_rn(acc[mi][ni][0] + b0, acc[mi][ni][1] + b1);
                *(__half2*)&g_proj[(size_t)(r + 8) * PROJW + cg] =
                    __floats2half2_rn(acc[mi][ni][2] + b0, acc[mi][ni][3] + b1);
            }
        }
    }
}

// ---------------------------------------------------------------------------
// Output GEMM (fp16, ldmatrix): out = g_att(128000x256) @ g_wo^T + g_ob.
// cp.async double-buffered 64-half k-chunks. Smem 72KB -> 2 CTAs/SM.
// ---------------------------------------------------------------------------
#define OUT_SMEM (4 * 128 * 72 * 2)

__global__ void __launch_bounds__(256, 2) gemm_out(float* __restrict__ C)
{
    extern __shared__ __half smh[];
    __half* Ab = smh;                    // 2 x [128][72]
    __half* Bb = smh + 2 * 128 * 72;     // 2 x [128][72]
    const uint32_t ab_u = (uint32_t)__cvta_generic_to_shared(Ab);
    const uint32_t bb_u = (uint32_t)__cvta_generic_to_shared(Bb);

    const int tid   = threadIdx.x;
    const int warp  = tid >> 5;
    const int lane  = tid & 31;
    const int group = lane >> 2;
    const int tg    = lane & 3;
    const int wm    = (warp & 1) * 64;
    const int wn    = (warp >> 1) * 32;

    const size_t arow0 = (size_t)blockIdx.x * 128;

    auto pref = [&](int c) {
        int kc = c * 64;
        uint32_t ab = ab_u + (c & 1) * (128 * 72 * 2);
        uint32_t bb = bb_u + (c & 1) * (128 * 72 * 2);
        #pragma unroll
        for (int i = 0; i < 4; i++) {
            int u   = i * 256 + tid;       // 0..1023
            int row = u >> 3;              // 0..127
            int c8  = u & 7;               // 8 x 8 halves per row
            uint32_t off = row * 144 + c8 * 16;
            cp16(ab + off, g_att + (arow0 + row) * 256 + kc + c8 * 8);
            cp16(bb + off, g_wo + (size_t)row * 256 + kc + c8 * 8);
        }
        CP_COMMIT();
    };

    pref(0);

    // ldmatrix offsets (stride 72 halves = 144B)
    const uint32_t a_off =
        (((wm + (lane & 15)) * 72 + ((lane >> 4) << 3)) << 1);
    const uint32_t b_off =
        (((wn + (lane & 7) + ((lane & 16) ? 8 : 0)) * 72 + ((lane & 8) ? 8 : 0)) << 1);

    float acc[4][4][4];
    #pragma unroll
    for (int mi = 0; mi < 4; mi++)
        #pragma unroll
        for (int ni = 0; ni < 4; ni++)
            #pragma unroll
            for (int r = 0; r < 4; r++) acc[mi][ni][r] = 0.f;

    for (int c = 0; c < 4; c++) {
        if (c + 1 < 4) { pref(c + 1); CP_WAIT(1); }
        else           { CP_WAIT(0); }
        __syncthreads();

        const uint32_t a_cur = ab_u + (c & 1) * (128 * 72 * 2) + a_off;
        const uint32_t b_cur = bb_u + (c & 1) * (128 * 72 * 2) + b_off;

        #pragma unroll
        for (int k0 = 0; k0 < 64; k0 += 16) {
            uint32_t af[4][4];
            uint32_t bf[4][2];
            #pragma unroll
            for (int mi = 0; mi < 4; mi++)
                ldsm_x4(af[mi][0], af[mi][1], af[mi][2], af[mi][3],
                        a_cur + mi * (16 * 72 * 2) + k0 * 2);
            ldsm_x4(bf[0][0], bf[0][1], bf[1][0], bf[1][1], b_cur + k0 * 2);
            ldsm_x4(bf[2][0], bf[2][1], bf[3][0], bf[3][1],
                    b_cur + (16 * 72 * 2) + k0 * 2);
            #pragma unroll
            for (int mi = 0; mi < 4; mi++)
                #pragma unroll
                for (int ni = 0; ni < 4; ni++)
                    mma_f16(acc[mi][ni], af[mi], bf[ni]);
        }
        __syncthreads();
    }

    const int row0 = (int)arow0 + wm + group;
    const int col0 = wn + tg * 2;
    #pragma unroll
    for (int ni = 0; ni < 4; ni++) {
        int c = col0 + ni * 8;
        float b0 = g_ob[c], b1 = g_ob[c + 1];
        #pragma unroll
        for (int mi = 0; mi < 4; mi++) {
            int r = row0 + mi * 16;
            *(float2*)&C[(size_t)r * 128 + c] =
                make_float2(acc[mi][ni][0] + b0, acc[mi][ni][1] + b1);
            *(float2*)&C[(size_t)(r + 8) * 128 + c] =
                make_float2(acc[mi][ni][2] + b0, acc[mi][ni][3] + b1);
        }
    }
}

// ---------------------------------------------------------------------------
// Merged attention: blocks [0,4000) temporal (block per (b,n)),
// blocks [4000,20000) spatial (warp per token). g_proj fp16 -> fp32 math.
// ---------------------------------------------------------------------------
#define TEMP_STRIDE 388   // 384 + 4 pad (floats)
#define TEMP_SMEM   (32 * TEMP_STRIDE * 4)

__global__ void __launch_bounds__(256) attn_kernel(const int* __restrict__ route)
{
    extern __shared__ float S[];   // [32][TEMP_STRIDE] fp32 (temporal only)

    const int tid  = threadIdx.x;

    if (blockIdx.x < 4000) {
        // ---------------- temporal ----------------
        const int wid  = tid >> 5;     // head
        const int lane = tid & 31;     // l
        const int n = blockIdx.x % N_;
        const int b = blockIdx.x / N_;

        #pragma unroll
        for (int i = 0; i < 6; i++) {
            int fid = i * 256 + tid;       // 0..1535
            int r   = fid / 48;
            int c8  = fid % 48;
            size_t m = ((size_t)r * B_ + b) * N_ + n;
            uint4 v = *(const uint4*)(g_proj + m * PROJW + c8 * 8);
            float* d = S + r * TEMP_STRIDE + c8 * 8;
            float2 f0 = __half22float2(*(__half2*)&v.x);
            float2 f1 = __half22float2(*(__half2*)&v.y);
            float2 f2 = __half22float2(*(__half2*)&v.z);
            float2 f3 = __half22float2(*(__half2*)&v.w);
            d[0] = f0.x; d[1] = f0.y; d[2] = f1.x; d[3] = f1.y;
            d[4] = f2.x; d[5] = f2.y; d[6] = f3.x; d[7] = f3.y;
        }
        __syncthreads();

        const int hoff = wid * DH_;
        float4 q[4];
        #pragma unroll
        for (int i = 0; i < 4; i++)
            q[i] = *(const float4*)(S + lane * TEMP_STRIDE + hoff + i * 4);

        float s[32];
        #pragma unroll
        for (int mm = 0; mm < 32; mm++) {
            const float* kr = S + mm * TEMP_STRIDE + 128 + hoff;
            float a = 0.f;
            #pragma unroll
            for (int i = 0; i < 4; i++) {
                float4 kv = *(const float4*)(kr + i * 4);   // broadcast
                a += q[i].x * kv.x + q[i].y * kv.y + q[i].z * kv.z + q[i].w * kv.w;
            }
            s[mm] = a * 0.25f;
        }

        float mx = s[0];
        #pragma unroll
        for (int mm = 1; mm < 32; mm++) mx = fmaxf(mx, s[mm]);
        float sum = 0.f;
        #pragma unroll
        for (int mm = 0; mm < 32; mm++) { s[mm] = __expf(s[mm] - mx); sum += s[mm]; }
        float inv = 1.f / sum;

        float4 o[4];
        #pragma unroll
        for (int i = 0; i < 4; i++) o[i] = make_float4(0.f, 0.f, 0.f, 0.f);
        #pragma unroll
        for (int mm = 0; mm < 32; mm++) {
            float p = s[mm] * inv;
            const float* vr = S + mm * TEMP_STRIDE + 256 + hoff;
            #pragma unroll
            for (int i = 0; i < 4; i++) {
                float4 vv = *(const float4*)(vr + i * 4);   // broadcast
                o[i].x += p * vv.x; o[i].y += p * vv.y;
                o[i].z += p * vv.z; o[i].w += p * vv.w;
            }
        }

        size_t m = ((size_t)lane * B_ + b) * N_ + n;
        __half2* orow = (__half2*)(g_att + m * 256 + hoff);
        #pragma unroll
        for (int i = 0; i < 4; i++) {
            orow[i * 2]     = __floats2half2_rn(o[i].x, o[i].y);
            orow[i * 2 + 1] = __floats2half2_rn(o[i].z, o[i].w);
        }
    } else {
        // ---------------- spatial (register-only) ----------------
        const int w    = tid >> 5;
        const int lane = tid & 31;
        const size_t m = (size_t)(blockIdx.x - 4000) * 8 + w;
        const int n    = (int)(m % N_);
        const size_t lbbase = m - n;               // row of (l, b, 0)

        float4 q4 = h4_to_f4(*(const uint2*)(g_proj + m * PROJW + 384 + lane * 4));

        int nbv = (lane < 8) ? route[n * 8 + lane] : 0;

        float s[8];
        float4 v4[8];
        #pragma unroll
        for (int kk = 0; kk < 8; kk++) {
            int nb = __shfl_sync(0xffffffffu, nbv, kk);
            const __half* r = g_proj + (lbbase + nb) * PROJW;
            float4 k4 = h4_to_f4(*(const uint2*)(r + 512 + lane * 4));
            v4[kk]    = h4_to_f4(*(const uint2*)(r + 640 + lane * 4));
            float part = q4.x * k4.x + q4.y * k4.y + q4.z * k4.z + q4.w * k4.w;
            part += __shfl_xor_sync(0xffffffffu, part, 1);
            part += __shfl_xor_sync(0xffffffffu, part, 2);
            s[kk] = part * 0.25f;
        }

        float mx = s[0];
        #pragma unroll
        for (int kk = 1; kk < 8; kk++) mx = fmaxf(mx, s[kk]);
        float sum = 0.f;
        #pragma unroll
        for (int kk = 0; kk < 8; kk++) { s[kk] = __expf(s[kk] - mx); sum += s[kk]; }
        float inv = 1.f / sum;

        float4 o = make_float4(0.f, 0.f, 0.f, 0.f);
        #pragma unroll
        for (int kk = 0; kk < 8; kk++) {
            float pb = s[kk] * inv;
            o.x += pb * v4[kk].x; o.y += pb * v4[kk].y;
            o.z += pb * v4[kk].z; o.w += pb * v4[kk].w;
        }
        __half2* dst = (__half2*)(g_att + m * 256 + 128 + lane * 4);
        dst[0] = __floats2half2_rn(o.x, o.y);
        dst[1] = __floats2half2_rn(o.z, o.w);
    }
}

// ---------------------------------------------------------------------------
extern "C" void kernel_launch(void* const* d_in, const int* in_sizes, int n_in,
                              void* d_out, int out_size)
{
    const float* x       = (const float*)d_in[0];
    const int*   route   = (const int*)  d_in[1];
    const float* t_in_w  = (const float*)d_in[2];
    const float* t_in_b  = (const float*)d_in[3];
    const float* t_out_w = (const float*)d_in[4];
    const float* t_out_b = (const float*)d_in[5];
    const float* s_in_w  = (const float*)d_in[6];
    const float* s_in_b  = (const float*)d_in[7];
    const float* s_out_w = (const float*)d_in[8];
    const float* s_out_b = (const float*)d_in[9];
    float* out = (float*)d_out;

    cudaFuncSetAttribute(gemm_proj,   cudaFuncAttributeMaxDynamicSharedMemorySize, PROJ_SMEM);
    cudaFuncSetAttribute(gemm_out,    cudaFuncAttributeMaxDynamicSharedMemorySize, OUT_SMEM);
    cudaFuncSetAttribute(attn_kernel, cudaFuncAttributeMaxDynamicSharedMemorySize, TEMP_SMEM);

    // 1) pack weights (fp16)
    prep_weights<<<516, 256>>>(t_in_w, t_in_b, s_in_w, s_in_b,
                               t_out_w, t_out_b, s_out_w, s_out_b);

    // 2) fused projection: x(128000x128) @ g_w^T + g_b -> g_proj (fp16)
    gemm_proj<<<M_ / 128, 256, PROJ_SMEM>>>(x);

    // 3) merged temporal + spatial attention -> g_att (fp16)
    attn_kernel<<<4000 + M_ / 8, 256, TEMP_SMEM>>>(route);

    // 4) out = g_att @ g_wo^T + g_ob
    gemm_out<<<M_ / 128, 256, OUT_SMEM>>>(out);
}